// round 13
// baseline (speedup 1.0000x reference)
#include <cuda_runtime.h>
#include <cuda_bf16.h>
#include <math.h>
#include <stdint.h>

#define Bn 512
#define Cn 256
#define Ln 196
#define Dn 512
#define XWST 136   // phase-1 Xt word stride (uint32)
#define WST2 104   // phase-2 A/B word stride
#define BOFFW 20800 // word offset of Xw / Aw region (after B: 200*104 words)

#define NT 1024    // threads per CTA (32 warps)

__device__ __forceinline__ uint32_t fu(float f) { return __float_as_uint(f); }
__device__ __forceinline__ int pw8(int w2) {    // word-perm: (word tig, tig+4) adjacent
    return (w2 & ~7) + ((w2 & 3) << 1) + ((w2 >> 2) & 1);
}

__device__ __forceinline__ void mma16(float* d, uint32_t a0, uint32_t a1, uint32_t a2,
                                      uint32_t a3, uint32_t b0, uint32_t b1) {
    asm volatile("mma.sync.aligned.m16n8k16.row.col.f32.bf16.bf16.f32 "
        "{%0,%1,%2,%3}, {%4,%5,%6,%7}, {%8,%9}, {%0,%1,%2,%3};"
        : "+f"(d[0]), "+f"(d[1]), "+f"(d[2]), "+f"(d[3])
        : "r"(a0), "r"(a1), "r"(a2), "r"(a3), "r"(b0), "r"(b1));
}

// ============================================================================
// Mega-kernel: one CTA per batch, 1024 threads (32 warps).
// smem: [Bw: 200x104 bf16x2 words][Xw: 208x136 (phase1) / Aw: 256x104 (phase2)]
// ============================================================================
__global__ __launch_bounds__(NT, 1) void k_main(
    const float* __restrict__ imf, const float* __restrict__ txt,
    const float* __restrict__ sam, const float* __restrict__ Wsim,
    const float* __restrict__ bsim, float* __restrict__ out)
{
    extern __shared__ float dyn[];          // 196,352 B
    __shared__ float s_im[Dn];
    __shared__ float red[3][32];
    __shared__ float s_simw[200];
    __shared__ __align__(16) float cs1[200];
    __shared__ __align__(16) float cs2[200];
    __shared__ __align__(16) float s_rsum[208];
    __shared__ float s_inv[256];

    int b = blockIdx.x, t = threadIdx.x, w = t >> 5, ln = t & 31;
    int g = ln >> 2, tig = ln & 3;
    const float* Sb = sam + (size_t)b * Cn * Ln;

    uint32_t* Bw = reinterpret_cast<uint32_t*>(dyn);          // 200 x WST2
    uint16_t* Bh = reinterpret_cast<uint16_t*>(dyn);          // halfword view of Bw

    // ---------------- Phase 0: simw; zero accumulators + B tile ----------------
    {
        float a0 = 0.f, c0 = 0.f;
        if (t < Dn) {
            a0 = imf[(size_t)b * Dn + t];
            c0 = txt[(size_t)b * Dn + t];
        }
        float ni = a0*a0, nt = c0*c0, ct = a0*c0;
        #pragma unroll
        for (int o = 16; o > 0; o >>= 1) {
            ni += __shfl_xor_sync(0xffffffffu, ni, o);
            nt += __shfl_xor_sync(0xffffffffu, nt, o);
            ct += __shfl_xor_sync(0xffffffffu, ct, o);
        }
        if (ln == 0) { red[0][w] = ni; red[1][w] = nt; red[2][w] = ct; }
        if (t < 200) { cs1[t] = 0.f; cs2[t] = 0.f; }
        if (t < 256) s_inv[t] = 0.f;
        if (t >= 256 && t < 464) s_rsum[t - 256] = 0.f;
        // zero B tile (pads must be 0; valid region fully overwritten later)
        {
            uint4* B4 = reinterpret_cast<uint4*>(dyn);
            for (int i = t; i < (200 * WST2) / 4; i += NT) B4[i] = make_uint4(0u,0u,0u,0u);
        }
        __syncthreads();
        float nI = 0.f, nT = 0.f, cT = 0.f;
        #pragma unroll
        for (int j = 0; j < 32; j++) { nI += red[0][j]; nT += red[1][j]; cT += red[2][j]; }
        float invI = 1.0f / fmaxf(sqrtf(nI), 1e-12f);
        float invT = 1.0f / fmaxf(sqrtf(nT), 1e-12f);
        float cross = cT * invI * invT;
        if (t < Dn) s_im[t] = imf[(size_t)b * Dn + t] * invI;
        __syncthreads();

        const float4* s4 = reinterpret_cast<const float4*>(s_im);
        for (int r = w; r < Ln; r += 32) {
            const float4* wr = reinterpret_cast<const float4*>(Wsim + (size_t)r * Dn);
            float acc = 0.f;
            #pragma unroll
            for (int i = 0; i < 4; i++) {
                float4 a = wr[ln + i * 32];
                float4 s = s4[ln + i * 32];
                acc += a.x*s.x + a.y*s.y + a.z*s.z + a.w*s.w;
            }
            #pragma unroll
            for (int o = 16; o > 0; o >>= 1) acc += __shfl_xor_sync(0xffffffffu, acc, o);
            if (ln == 0) {
                acc += bsim[r];
                s_simw[r] = cross * (1.0f / (1.0f + __expf(-acc))) * 0.1f;
            }
        }
    }
    __syncthreads();

    // ---------------- Phase 1: GEMM1 (bf16) -> bf16 raw exp -> B tile (smem) ---
    {
        uint32_t* Xw = reinterpret_cast<uint32_t*>(dyn) + BOFFW;   // 208 x XWST

        // column norms, coalesced: thread -> column l = t&255, chunk = t>>8
        {
            int l = t & 255, ch = t >> 8;
            if (l < Ln) {
                const float* p = Sb + (size_t)(ch * 64) * Ln + l;
                float s0 = 0.f, s1 = 0.f;
                #pragma unroll 8
                for (int c = 0; c < 64; c += 2) {
                    float v0 = p[c * Ln], v1 = p[(c + 1) * Ln];
                    s0 += v0 * v0; s1 += v1 * v1;
                }
                atomicAdd(&s_inv[l], s0 + s1);
            }
        }
        for (int i = t; i < 12 * XWST; i += NT) Xw[196 * XWST + i] = 0u;
        __syncthreads();
        if (t < Ln) s_inv[t] = 0.25f / fmaxf(sqrtf(s_inv[t]), 1e-12f);
        __syncthreads();

        // stage X as bf16, scaled, c-word-permuted (incremental index: 1024=20*49+44)
        {
            int c2 = t / 49, l4 = t - c2 * 49;
            for (int idx = t; idx < 128 * 49; idx += NT) {
                int l0 = l4 * 4;
                float4 v0 = *reinterpret_cast<const float4*>(Sb + (size_t)(2*c2)   * Ln + l0);
                float4 v1 = *reinterpret_cast<const float4*>(Sb + (size_t)(2*c2+1) * Ln + l0);
                int wp = pw8(c2);
                float i0 = s_inv[l0], i1 = s_inv[l0+1], i2 = s_inv[l0+2], i3 = s_inv[l0+3];
                __nv_bfloat162 h0 = __floats2bfloat162_rn(v0.x * i0, v1.x * i0);
                __nv_bfloat162 h1 = __floats2bfloat162_rn(v0.y * i1, v1.y * i1);
                __nv_bfloat162 h2 = __floats2bfloat162_rn(v0.z * i2, v1.z * i2);
                __nv_bfloat162 h3 = __floats2bfloat162_rn(v0.w * i3, v1.w * i3);
                Xw[(l0+0) * XWST + wp] = *reinterpret_cast<uint32_t*>(&h0);
                Xw[(l0+1) * XWST + wp] = *reinterpret_cast<uint32_t*>(&h1);
                Xw[(l0+2) * XWST + wp] = *reinterpret_cast<uint32_t*>(&h2);
                Xw[(l0+3) * XWST + wp] = *reinterpret_cast<uint32_t*>(&h3);
                l4 += 44; c2 += 20;
                if (l4 >= 49) { l4 -= 49; c2 += 1; }
            }
        }
        __syncthreads();

        // 64 balanced jobs: mt0 -> (7,6,6,6) frag slices; mt1..12 -> 5x5.
        // warp w takes jobs w and 63-w (totals 10-12 frags vs ideal 10.2).
        #pragma unroll
        for (int r = 0; r < 2; r++) {
            int job = r ? (63 - w) : w;
            int mt, cb, nfr;
            if (job < 4) {
                mt = 0;
                nfr = (job == 0) ? 7 : 6;
                cb  = (job == 0) ? 0 : (56 + (job - 1) * 48);   // 0,56,104,152
            } else {
                int j = job - 4;
                mt = 1 + j / 5;
                cb = (j % 5) * 40;
                nfr = 5;
            }

            float acc[7][4];
            #pragma unroll
            for (int n = 0; n < 7; n++)
                #pragma unroll
                for (int j2 = 0; j2 < 4; j2++) acc[n][j2] = 0.f;

            const uint32_t* A0 = Xw + (mt * 16 + g) * XWST + 2 * tig;
            const uint32_t* A1 = A0 + 8 * XWST;
            const uint32_t* Bb = Xw + (cb + g) * XWST + 2 * tig;
            #pragma unroll 4
            for (int ks = 0; ks < 16; ks++) {
                uint2 av0 = *reinterpret_cast<const uint2*>(A0 + ks * 8);
                uint2 av1 = *reinterpret_cast<const uint2*>(A1 + ks * 8);
                #pragma unroll
                for (int n = 0; n < 7; n++) {
                    if (n < nfr) {
                        uint2 bv = *reinterpret_cast<const uint2*>(Bb + n * 8 * XWST + ks * 8);
                        mma16(acc[n], av0.x, av1.x, av0.y, av1.y, bv.x, bv.y);
                    }
                }
            }

            // epilogue: exp -> row sums + bf16 store straight into B tile
            // (symmetry: exp[l][m] = exp[m][l]; thread writes B rows m, m+1 at k=l)
            #pragma unroll
            for (int rh = 0; rh < 2; rh++) {
                int l = mt * 16 + g + 8 * rh;
                float e[7][2];
                float sum = 0.f;
                #pragma unroll
                for (int n = 0; n < 7; n++) {
                    if (n < nfr) {
                        int col0 = cb + n * 8 + 2 * tig;
                        float e0 = __expf(acc[n][rh*2]);
                        float e1 = __expf(acc[n][rh*2+1]);
                        e[n][0] = e0; e[n][1] = e1;
                        if (col0 < Ln) sum += e0 + e1;
                    }
                }
                sum += __shfl_xor_sync(0xffffffffu, sum, 1);
                sum += __shfl_xor_sync(0xffffffffu, sum, 2);
                if (l < Ln) {
                    if (tig == 0) atomicAdd(&s_rsum[l], sum);
                    int hw = pw8(l >> 1) * 2 + (l & 1);
                    #pragma unroll
                    for (int n = 0; n < 7; n++) {
                        if (n < nfr) {
                            int col0 = cb + n * 8 + 2 * tig;
                            if (col0 < Ln) {
                                __nv_bfloat16 h0 = __float2bfloat16(e[n][0]);
                                __nv_bfloat16 h1 = __float2bfloat16(e[n][1]);
                                Bh[col0 * (2 * WST2) + hw]       = *reinterpret_cast<uint16_t*>(&h0);
                                Bh[(col0 + 1) * (2 * WST2) + hw] = *reinterpret_cast<uint16_t*>(&h1);
                            }
                        }
                    }
                }
            }
        }
    }
    __syncthreads();
    if (t < Ln) s_rsum[t] = 1.0f / s_rsum[t];
    __syncthreads();

    // ---------------- Phase 2: GEMM2 (bf16); B already resident ----------------
    {
        uint32_t* Aw = reinterpret_cast<uint32_t*>(dyn) + BOFFW;   // 256 x WST2

        // stage A'[c][pw(w2)] = bf16x2(sam[c][l] / rsum[l]); vectorized,
        // incremental index over (c, g4): 6656 iters total, 1024 = 39*26 + 10
        {
            int c = t / 26, g4 = t - c * 26;
            for (int idx = t; idx < 256 * 26; idx += NT) {
                int l0 = g4 * 8;
                float4 va = make_float4(0.f, 0.f, 0.f, 0.f);
                float4 vb = make_float4(0.f, 0.f, 0.f, 0.f);
                const float* src = Sb + (size_t)c * Ln + l0;
                if (l0 < Ln) va = *reinterpret_cast<const float4*>(src);
                if (l0 + 4 < Ln) vb = *reinterpret_cast<const float4*>(src + 4);
                float4 r0 = *reinterpret_cast<const float4*>(s_rsum + l0);
                float4 r1 = *reinterpret_cast<const float4*>(s_rsum + l0 + 4);
                __nv_bfloat162 h0 = __floats2bfloat162_rn(va.x * r0.x, va.y * r0.y);
                __nv_bfloat162 h1 = __floats2bfloat162_rn(va.z * r0.z, va.w * r0.w);
                __nv_bfloat162 h2 = __floats2bfloat162_rn(vb.x * r1.x, vb.y * r1.y);
                __nv_bfloat162 h3 = __floats2bfloat162_rn(vb.z * r1.z, vb.w * r1.w);
                uint32_t* dst = Aw + c * WST2;
                int w2 = g4 * 4;
                dst[pw8(w2)]     = *reinterpret_cast<uint32_t*>(&h0);
                dst[pw8(w2 + 1)] = *reinterpret_cast<uint32_t*>(&h1);
                dst[pw8(w2 + 2)] = *reinterpret_cast<uint32_t*>(&h2);
                dst[pw8(w2 + 3)] = *reinterpret_cast<uint32_t*>(&h3);
                g4 += 10; c += 39;
                if (g4 >= 26) { g4 -= 26; c += 1; }
            }
        }
        __syncthreads();

        // 64 jobs, q-paired across rounds: warp does q then 3-q (totals 12/13).
        #pragma unroll
        for (int r = 0; r < 2; r++) {
            int q = r ? (3 - (w & 3)) : (w & 3);
            int mt = (w >> 2) + r * 8;
            int cbm = (q == 0) ? 0 : (q == 1) ? 56 : (q == 2) ? 104 : 160;
            int nfr = (q == 0 || q == 2) ? 7 : (q == 1) ? 6 : 5;

            float acc[7][4];
            #pragma unroll
            for (int n = 0; n < 7; n++)
                #pragma unroll
                for (int j = 0; j < 4; j++) acc[n][j] = 0.f;

            const uint32_t* A0 = Aw + (mt * 16 + g) * WST2 + 2 * tig;
            const uint32_t* A1 = A0 + 8 * WST2;
            const uint32_t* Bb = Bw + (cbm + g) * WST2 + 2 * tig;
            #pragma unroll 4
            for (int ks = 0; ks < 13; ks++) {
                uint2 av0 = *reinterpret_cast<const uint2*>(A0 + ks * 8);
                uint2 av1 = *reinterpret_cast<const uint2*>(A1 + ks * 8);
                #pragma unroll
                for (int n = 0; n < 7; n++) {
                    if (n < nfr) {
                        uint2 bv = *reinterpret_cast<const uint2*>(Bb + n * 8 * WST2 + ks * 8);
                        mma16(acc[n], av0.x, av1.x, av0.y, av1.y, bv.x, bv.y);
                    }
                }
            }

            // epilogue: y = sam + D -> out ONLY (stats in coalesced pass below)
            int c0r = mt * 16 + g;
            int c1r = c0r + 8;
            const float* S0 = Sb + (size_t)c0r * Ln;
            const float* S1 = Sb + (size_t)c1r * Ln;
            float* O0 = out + ((size_t)b * Cn + c0r) * Ln;
            float* O1 = out + ((size_t)b * Cn + c1r) * Ln;
            #pragma unroll
            for (int n = 0; n < 7; n++) {
                if (n < nfr) {
                    int col0 = cbm + n * 8 + 2 * tig;
                    if (col0 < Ln) {
                        float2 s0 = *reinterpret_cast<const float2*>(S0 + col0);
                        float2 s1 = *reinterpret_cast<const float2*>(S1 + col0);
                        *reinterpret_cast<float2*>(O0 + col0) =
                            make_float2(s0.x + acc[n][0], s0.y + acc[n][1]);
                        *reinterpret_cast<float2*>(O1 + col0) =
                            make_float2(s1.x + acc[n][2], s1.y + acc[n][3]);
                    }
                }
            }
        }
    }
    __syncthreads();

    // ---------------- Phase 2b: column stats from out (L2-hot, coalesced) ------
    {
        int l = t & 255, ch = t >> 8;       // ch in 0..3, 64 rows each
        if (l < Ln) {
            const float* p = out + (size_t)b * Cn * Ln + (size_t)(ch * 64) * Ln + l;
            float s1 = 0.f, s2 = 0.f;
            #pragma unroll 8
            for (int c = 0; c < 64; c += 2) {
                float v0 = p[c * Ln], v1 = p[(c + 1) * Ln];
                s1 += v0 + v1;
                s2 += v0 * v0 + v1 * v1;
            }
            atomicAdd(&cs1[l], s1);
            atomicAdd(&cs2[l], s2);
        }
    }
    __syncthreads();

    // ---------------- Phase 3: channel-LN affine P,Q ----------------
    if (t < Ln) {
        float a = 0.5f * s_simw[t];
        float mu_y  = cs1[t] * (1.0f / Cn);
        float var_y = cs2[t] * (1.0f / Cn) - mu_y * mu_y;
        float inv_s = rsqrtf(a * a * var_y + 1e-5f);
        cs1[t] = a * inv_s;
        cs2[t] = -a * mu_y * inv_s;
    }
    if (t >= Ln && t < 200) { cs1[t] = 0.f; cs2[t] = 0.f; }
    __syncthreads();

    // ---------------- Phase 4: spatial standardization (out L2-hot) ----------
    {
        const float4* P4 = reinterpret_cast<const float4*>(cs1);
        const float4* Q4 = reinterpret_cast<const float4*>(cs2);
        bool has2 = (ln + 32) < Ln / 4;
        int g2 = has2 ? (ln + 32) : 0;
        float4 p0 = P4[ln], q0 = Q4[ln];
        float4 p1 = P4[g2], q1 = Q4[g2];

        for (int c = w; c < Cn; c += 32) {
            float4* orow = reinterpret_cast<float4*>(out + ((size_t)b * Cn + c) * Ln);
            float4 y0 = orow[ln];
            float x0[4] = { fmaf(y0.x, p0.x, q0.x), fmaf(y0.y, p0.y, q0.y),
                            fmaf(y0.z, p0.z, q0.z), fmaf(y0.w, p0.w, q0.w) };
            float x1[4] = { 0.f, 0.f, 0.f, 0.f };
            if (has2) {
                float4 y1 = orow[g2];
                x1[0] = fmaf(y1.x, p1.x, q1.x); x1[1] = fmaf(y1.y, p1.y, q1.y);
                x1[2] = fmaf(y1.z, p1.z, q1.z); x1[3] = fmaf(y1.w, p1.w, q1.w);
            }
            float s1 = x0[0] + x0[1] + x0[2] + x0[3];
            float s2 = x0[0]*x0[0] + x0[1]*x0[1] + x0[2]*x0[2] + x0[3]*x0[3];
            if (has2) {
                s1 += x1[0] + x1[1] + x1[2] + x1[3];
                s2 += x1[0]*x1[0] + x1[1]*x1[1] + x1[2]*x1[2] + x1[3]*x1[3];
            }
            #pragma unroll
            for (int o = 16; o > 0; o >>= 1) {
                s1 += __shfl_xor_sync(0xffffffffu, s1, o);
                s2 += __shfl_xor_sync(0xffffffffu, s2, o);
            }
            float mean = s1 * (1.0f / Ln);
            float var  = (s2 - (float)Ln * mean * mean) * (1.0f / (Ln - 1));
            float inv  = 1.0f / (sqrtf(fmaxf(var, 0.f)) + 1e-6f);

            float4 o0 = { (x0[0]-mean)*inv, (x0[1]-mean)*inv, (x0[2]-mean)*inv, (x0[3]-mean)*inv };
            orow[ln] = o0;
            if (has2) {
                float4 o1 = { (x1[0]-mean)*inv, (x1[1]-mean)*inv, (x1[2]-mean)*inv, (x1[3]-mean)*inv };
                orow[g2] = o1;
            }
        }
    }
}

// ============================================================================
extern "C" void kernel_launch(void* const* d_in, const int* in_sizes, int n_in,
                              void* d_out, int out_size)
{
    const float* imf  = (const float*)d_in[0];
    const float* txt  = (const float*)d_in[1];
    const float* sam  = (const float*)d_in[2];
    const float* Wsim = (const float*)d_in[3];
    const float* bsim = (const float*)d_in[4];
    float* out = (float*)d_out;

    // B (200*104 words) + max(Xw 208*136, Aw 256*104) words = 49,088 words
    const int smem = (BOFFW + 208 * XWST) * (int)sizeof(float);   // 196,352 B
    cudaFuncSetAttribute(k_main, cudaFuncAttributeMaxDynamicSharedMemorySize, smem);
    k_main<<<Bn, NT, smem>>>(imf, txt, sam, Wsim, bsim, out);
}

// round 14
// speedup vs baseline: 1.0238x; 1.0238x over previous
#include <cuda_runtime.h>
#include <cuda_bf16.h>
#include <math.h>
#include <stdint.h>

#define Bn 512
#define Cn 256
#define Ln 196
#define Dn 512
#define XWST 136    // phase-1 X word stride: 68 8B-units == 4 mod 32 -> conflict-free
#define WST2 104    // phase-2 A/B word stride: 52 units == 20 mod 32 -> conflict-free
#define BWRDS 20800 // B tile words (200 x 104)
#define NT 512      // threads per CTA (16 warps) -> 2 CTAs/SM

// raw exp matrix, bf16x2 words: [b][l][98 words] (96+2 valid = 196 bf16 cols)
static __device__ uint32_t g_attnw[(size_t)Bn * Ln * 98];

__device__ __forceinline__ uint32_t fu(float f) { return __float_as_uint(f); }
__device__ __forceinline__ int pw8(int w2) {    // word-perm: (word tig, tig+4) adjacent
    return (w2 & ~7) + ((w2 & 3) << 1) + ((w2 >> 2) & 1);
}

__device__ __forceinline__ void mma16(float* d, uint32_t a0, uint32_t a1, uint32_t a2,
                                      uint32_t a3, uint32_t b0, uint32_t b1) {
    asm volatile("mma.sync.aligned.m16n8k16.row.col.f32.bf16.bf16.f32 "
        "{%0,%1,%2,%3}, {%4,%5,%6,%7}, {%8,%9}, {%0,%1,%2,%3};"
        : "+f"(d[0]), "+f"(d[1]), "+f"(d[2]), "+f"(d[3])
        : "r"(a0), "r"(a1), "r"(a2), "r"(a3), "r"(b0), "r"(b1));
}

// ============================================================================
// Mega-kernel: one CTA per batch, 512 threads (16 warps), 2 CTAs/SM.
// dyn smem: phase1 Xw 200x136 words; phase2 [Bw 200x104][A-slice 64x104].
// ============================================================================
__global__ __launch_bounds__(NT, 2) void k_main(
    const float* __restrict__ imf, const float* __restrict__ txt,
    const float* __restrict__ sam, const float* __restrict__ Wsim,
    const float* __restrict__ bsim, float* __restrict__ out)
{
    extern __shared__ float dyn[];          // 109,824 B
    __shared__ float red[3][16];
    __shared__ float s_simw[200];
    __shared__ __align__(16) float cs1[200];
    __shared__ __align__(16) float cs2[200];
    __shared__ __align__(16) float s_rsum[208];
    __shared__ float s_inv[208];

    int b = blockIdx.x, t = threadIdx.x, w = t >> 5, ln = t & 31;
    int g = ln >> 2, tig = ln & 3;
    const float* Sb = sam + (size_t)b * Cn * Ln;
    uint32_t* Ag = g_attnw + (size_t)b * Ln * 98;

    // ---------------- Phase 0: simw (s_im lives in dyn); zero accums ----------
    {
        float* s_imd = dyn;                 // 512 floats, phase-0 only
        float a0 = imf[(size_t)b * Dn + t];
        float c0 = txt[(size_t)b * Dn + t];
        float ni = a0*a0, nt = c0*c0, ct = a0*c0;
        #pragma unroll
        for (int o = 16; o > 0; o >>= 1) {
            ni += __shfl_xor_sync(0xffffffffu, ni, o);
            nt += __shfl_xor_sync(0xffffffffu, nt, o);
            ct += __shfl_xor_sync(0xffffffffu, ct, o);
        }
        if (ln == 0) { red[0][w] = ni; red[1][w] = nt; red[2][w] = ct; }
        if (t < 200) { cs1[t] = 0.f; cs2[t] = 0.f; }
        if (t < 208) { s_inv[t] = 0.f; s_rsum[t] = 0.f; }
        __syncthreads();
        float nI = 0.f, nT = 0.f, cT = 0.f;
        #pragma unroll
        for (int j = 0; j < 16; j++) { nI += red[0][j]; nT += red[1][j]; cT += red[2][j]; }
        float invI = 1.0f / fmaxf(sqrtf(nI), 1e-12f);
        float invT = 1.0f / fmaxf(sqrtf(nT), 1e-12f);
        float cross = cT * invI * invT;
        s_imd[t] = a0 * invI;
        __syncthreads();

        const float4* s4 = reinterpret_cast<const float4*>(s_imd);
        for (int r = w; r < Ln; r += 16) {
            const float4* wr = reinterpret_cast<const float4*>(Wsim + (size_t)r * Dn);
            float acc = 0.f;
            #pragma unroll
            for (int i = 0; i < 4; i++) {
                float4 a = wr[ln + i * 32];
                float4 s = s4[ln + i * 32];
                acc += a.x*s.x + a.y*s.y + a.z*s.z + a.w*s.w;
            }
            #pragma unroll
            for (int o = 16; o > 0; o >>= 1) acc += __shfl_xor_sync(0xffffffffu, acc, o);
            if (ln == 0) {
                acc += bsim[r];
                s_simw[r] = cross * (1.0f / (1.0f + __expf(-acc))) * 0.1f;
            }
        }
    }
    __syncthreads();

    // ---------------- Phase 1: GEMM1 (bf16) -> bf16 raw exp -> g_attnw --------
    {
        uint32_t* Xw = reinterpret_cast<uint32_t*>(dyn);   // 200 x XWST

        // column norms, coalesced: l = t&255, ch = t>>8 (2 chunks of 128 rows)
        {
            int l = t & 255, ch = t >> 8;
            if (l < Ln) {
                const float* p = Sb + (size_t)(ch * 128) * Ln + l;
                float s0 = 0.f, s1 = 0.f;
                #pragma unroll 8
                for (int c = 0; c < 128; c += 2) {
                    float v0 = p[c * Ln], v1 = p[(c + 1) * Ln];
                    s0 += v0 * v0; s1 += v1 * v1;
                }
                atomicAdd(&s_inv[l], s0 + s1);
            }
        }
        __syncthreads();
        if (t < Ln) s_inv[t] = 0.25f / fmaxf(sqrtf(s_inv[t]), 1e-12f);
        __syncthreads();

        // stage X bf16, scaled, c-word-permuted (incremental: 512 = 10*49 + 22)
        {
            int c2 = t / 49, l4 = t - c2 * 49;
            for (int idx = t; idx < 128 * 49; idx += NT) {
                int l0 = l4 * 4;
                float4 v0 = *reinterpret_cast<const float4*>(Sb + (size_t)(2*c2)   * Ln + l0);
                float4 v1 = *reinterpret_cast<const float4*>(Sb + (size_t)(2*c2+1) * Ln + l0);
                int wp = pw8(c2);
                float i0 = s_inv[l0], i1 = s_inv[l0+1], i2 = s_inv[l0+2], i3 = s_inv[l0+3];
                __nv_bfloat162 h0 = __floats2bfloat162_rn(v0.x * i0, v1.x * i0);
                __nv_bfloat162 h1 = __floats2bfloat162_rn(v0.y * i1, v1.y * i1);
                __nv_bfloat162 h2 = __floats2bfloat162_rn(v0.z * i2, v1.z * i2);
                __nv_bfloat162 h3 = __floats2bfloat162_rn(v0.w * i3, v1.w * i3);
                Xw[(l0+0) * XWST + wp] = *reinterpret_cast<uint32_t*>(&h0);
                Xw[(l0+1) * XWST + wp] = *reinterpret_cast<uint32_t*>(&h1);
                Xw[(l0+2) * XWST + wp] = *reinterpret_cast<uint32_t*>(&h2);
                Xw[(l0+3) * XWST + wp] = *reinterpret_cast<uint32_t*>(&h3);
                l4 += 22; c2 += 10;
                if (l4 >= 49) { l4 -= 49; c2 += 1; }
            }
        }
        __syncthreads();

        // 64 jobs over 4 rounds x 16 warps.
        // jobs 0..3: mt0 slices (7,6,6,6); jobs 4..63: mt 1..12 x 5 slices of 5.
        for (int r = 0; r < 4; r++) {
            int job = r * 16 + w;
            int mt, cb, nfr;
            if (job < 4) {
                mt = 0;
                nfr = (job == 0) ? 7 : 6;
                cb  = (job == 0) ? 0 : (56 + (job - 1) * 48);
            } else {
                int j = job - 4;
                mt = 1 + j / 5;
                cb = (j % 5) * 40;
                nfr = 5;
            }
            bool tail = (mt == 12);   // rows 200..207 don't exist: reuse av0

            float acc[7][4];
            #pragma unroll
            for (int n = 0; n < 7; n++)
                #pragma unroll
                for (int j2 = 0; j2 < 4; j2++) acc[n][j2] = 0.f;

            const uint32_t* A0 = Xw + (mt * 16 + g) * XWST + 2 * tig;
            const uint32_t* A1 = A0 + 8 * XWST;
            const uint32_t* Bb = Xw + (cb + g) * XWST + 2 * tig;
            #pragma unroll 4
            for (int ks = 0; ks < 16; ks++) {
                uint2 av0 = *reinterpret_cast<const uint2*>(A0 + ks * 8);
                uint2 av1 = tail ? av0 : *reinterpret_cast<const uint2*>(A1 + ks * 8);
                #pragma unroll
                for (int n = 0; n < 7; n++) {
                    if (n < nfr) {
                        uint2 bv = *reinterpret_cast<const uint2*>(Bb + n * 8 * XWST + ks * 8);
                        mma16(acc[n], av0.x, av1.x, av0.y, av1.y, bv.x, bv.y);
                    }
                }
            }

            // epilogue: exp -> row sums + bf16x2 store to g_attnw row l
            #pragma unroll
            for (int rh = 0; rh < 2; rh++) {
                int l = mt * 16 + g + 8 * rh;
                float e[7][2];
                float sum = 0.f;
                #pragma unroll
                for (int n = 0; n < 7; n++) {
                    if (n < nfr) {
                        int col0 = cb + n * 8 + 2 * tig;
                        float e0 = __expf(acc[n][rh*2]);
                        float e1 = __expf(acc[n][rh*2+1]);
                        e[n][0] = e0; e[n][1] = e1;
                        if (col0 < Ln) sum += e0 + e1;
                    }
                }
                sum += __shfl_xor_sync(0xffffffffu, sum, 1);
                sum += __shfl_xor_sync(0xffffffffu, sum, 2);
                if (l < Ln) {
                    if (tig == 0) atomicAdd(&s_rsum[l], sum);
                    uint32_t* arow = Ag + (size_t)l * 98;
                    #pragma unroll
                    for (int n = 0; n < 7; n++) {
                        if (n < nfr) {
                            int col0 = cb + n * 8 + 2 * tig;
                            if (col0 < Ln) {
                                __nv_bfloat162 h = __floats2bfloat162_rn(e[n][0], e[n][1]);
                                arow[col0 >> 1] = *reinterpret_cast<uint32_t*>(&h);
                            }
                        }
                    }
                }
            }
        }
    }
    __syncthreads();
    if (t < Ln) s_rsum[t] = 1.0f / s_rsum[t];
    __syncthreads();

    // ---------------- Phase 2: GEMM2 (bf16); B resident, A in 64-row slices ----
    {
        uint32_t* Bw = reinterpret_cast<uint32_t*>(dyn);          // 200 x 104
        uint32_t* Aw = reinterpret_cast<uint32_t*>(dyn) + BWRDS;  // 64 x 104

        // stage B[m][pw(w2)] from g_attnw (raw exp bf16; rsum folded into A)
        {
            int m = t / 52, p2 = t - m * 52;      // 512 = 9*52 + 44
            for (int idx = t; idx < 200 * 52; idx += NT) {
                int w2 = 2 * p2;
                uint2 v = make_uint2(0u, 0u);
                if (m < Ln && w2 < 98)
                    v = *reinterpret_cast<const uint2*>(g_attnw + ((size_t)b * Ln + m) * 98 + w2);
                Bw[m * WST2 + pw8(w2)]     = v.x;
                Bw[m * WST2 + pw8(w2 + 1)] = v.y;
                p2 += 44; m += 9;
                if (p2 >= 52) { p2 -= 52; m += 1; }
            }
        }

        for (int r = 0; r < 4; r++) {
            __syncthreads();
            // stage A slice rows [64r, 64r+64): A'[c][l] = bf16(sam[c][l]/rsum[l])
            {
                int cl = t / 26, g4 = t - cl * 26;   // 512 = 19*26 + 18
                for (int idx = t; idx < 64 * 26; idx += NT) {
                    int c = 64 * r + cl;
                    int l0 = g4 * 8;
                    float4 va = make_float4(0.f, 0.f, 0.f, 0.f);
                    float4 vb = make_float4(0.f, 0.f, 0.f, 0.f);
                    const float* src = Sb + (size_t)c * Ln + l0;
                    if (l0 < Ln) va = *reinterpret_cast<const float4*>(src);
                    if (l0 + 4 < Ln) vb = *reinterpret_cast<const float4*>(src + 4);
                    float4 r0 = *reinterpret_cast<const float4*>(s_rsum + l0);
                    float4 r1 = *reinterpret_cast<const float4*>(s_rsum + l0 + 4);
                    __nv_bfloat162 h0 = __floats2bfloat162_rn(va.x * r0.x, va.y * r0.y);
                    __nv_bfloat162 h1 = __floats2bfloat162_rn(va.z * r0.z, va.w * r0.w);
                    __nv_bfloat162 h2 = __floats2bfloat162_rn(vb.x * r1.x, vb.y * r1.y);
                    __nv_bfloat162 h3 = __floats2bfloat162_rn(vb.z * r1.z, vb.w * r1.w);
                    uint32_t* dst = Aw + cl * WST2;
                    int w2 = g4 * 4;
                    dst[pw8(w2)]     = *reinterpret_cast<uint32_t*>(&h0);
                    dst[pw8(w2 + 1)] = *reinterpret_cast<uint32_t*>(&h1);
                    dst[pw8(w2 + 2)] = *reinterpret_cast<uint32_t*>(&h2);
                    dst[pw8(w2 + 3)] = *reinterpret_cast<uint32_t*>(&h3);
                    g4 += 18; cl += 19;
                    if (g4 >= 26) { g4 -= 26; cl += 1; }
                }
            }
            __syncthreads();

            // 16 jobs this round: mt = 4r + w/4 (global), q rotated for balance
            int q = (r + w) & 3;
            int mtl = (w >> 2);                       // local m-tile in slice
            int mtg = 4 * r + mtl;                    // global m-tile
            int cbm = (q == 0) ? 0 : (q == 1) ? 56 : (q == 2) ? 104 : 160;
            int nfr = (q == 0 || q == 2) ? 7 : (q == 1) ? 6 : 5;

            float acc[7][4];
            #pragma unroll
            for (int n = 0; n < 7; n++)
                #pragma unroll
                for (int j = 0; j < 4; j++) acc[n][j] = 0.f;

            const uint32_t* A0 = Aw + (mtl * 16 + g) * WST2 + 2 * tig;
            const uint32_t* A1 = A0 + 8 * WST2;
            const uint32_t* Bb = Bw + (cbm + g) * WST2 + 2 * tig;
            #pragma unroll 4
            for (int ks = 0; ks < 13; ks++) {
                uint2 av0 = *reinterpret_cast<const uint2*>(A0 + ks * 8);
                uint2 av1 = *reinterpret_cast<const uint2*>(A1 + ks * 8);
                #pragma unroll
                for (int n = 0; n < 7; n++) {
                    if (n < nfr) {
                        uint2 bv = *reinterpret_cast<const uint2*>(Bb + n * 8 * WST2 + ks * 8);
                        mma16(acc[n], av0.x, av1.x, av0.y, av1.y, bv.x, bv.y);
                    }
                }
            }

            // epilogue: y = sam + D -> out (stats in coalesced pass below)
            int c0r = mtg * 16 + g;
            int c1r = c0r + 8;
            const float* S0 = Sb + (size_t)c0r * Ln;
            const float* S1 = Sb + (size_t)c1r * Ln;
            float* O0 = out + ((size_t)b * Cn + c0r) * Ln;
            float* O1 = out + ((size_t)b * Cn + c1r) * Ln;
            #pragma unroll
            for (int n = 0; n < 7; n++) {
                if (n < nfr) {
                    int col0 = cbm + n * 8 + 2 * tig;
                    if (col0 < Ln) {
                        float2 s0 = *reinterpret_cast<const float2*>(S0 + col0);
                        float2 s1 = *reinterpret_cast<const float2*>(S1 + col0);
                        *reinterpret_cast<float2*>(O0 + col0) =
                            make_float2(s0.x + acc[n][0], s0.y + acc[n][1]);
                        *reinterpret_cast<float2*>(O1 + col0) =
                            make_float2(s1.x + acc[n][2], s1.y + acc[n][3]);
                    }
                }
            }
        }
    }
    __syncthreads();

    // ---------------- Phase 2b: column stats from out (L2-hot, coalesced) ------
    {
        int l = t & 255, ch = t >> 8;       // ch 0..1, 128 rows each
        if (l < Ln) {
            const float* p = out + (size_t)b * Cn * Ln + (size_t)(ch * 128) * Ln + l;
            float s1 = 0.f, s2 = 0.f;
            #pragma unroll 8
            for (int c = 0; c < 128; c += 2) {
                float v0 = p[c * Ln], v1 = p[(c + 1) * Ln];
                s1 += v0 + v1;
                s2 += v0 * v0 + v1 * v1;
            }
            atomicAdd(&cs1[l], s1);
            atomicAdd(&cs2[l], s2);
        }
    }
    __syncthreads();

    // ---------------- Phase 3: channel-LN affine P,Q ----------------
    if (t < Ln) {
        float a = 0.5f * s_simw[t];
        float mu_y  = cs1[t] * (1.0f / Cn);
        float var_y = cs2[t] * (1.0f / Cn) - mu_y * mu_y;
        float inv_s = rsqrtf(a * a * var_y + 1e-5f);
        cs1[t] = a * inv_s;
        cs2[t] = -a * mu_y * inv_s;
    }
    if (t >= Ln && t < 200) { cs1[t] = 0.f; cs2[t] = 0.f; }
    __syncthreads();

    // ---------------- Phase 4: spatial standardization (out L2-hot) ----------
    {
        const float4* P4 = reinterpret_cast<const float4*>(cs1);
        const float4* Q4 = reinterpret_cast<const float4*>(cs2);
        bool has2 = (ln + 32) < Ln / 4;
        int g2 = has2 ? (ln + 32) : 0;
        float4 p0 = P4[ln], q0 = Q4[ln];
        float4 p1 = P4[g2], q1 = Q4[g2];

        for (int c = w; c < Cn; c += 16) {
            float4* orow = reinterpret_cast<float4*>(out + ((size_t)b * Cn + c) * Ln);
            float4 y0 = orow[ln];
            float x0[4] = { fmaf(y0.x, p0.x, q0.x), fmaf(y0.y, p0.y, q0.y),
                            fmaf(y0.z, p0.z, q0.z), fmaf(y0.w, p0.w, q0.w) };
            float x1[4] = { 0.f, 0.f, 0.f, 0.f };
            if (has2) {
                float4 y1 = orow[g2];
                x1[0] = fmaf(y1.x, p1.x, q1.x); x1[1] = fmaf(y1.y, p1.y, q1.y);
                x1[2] = fmaf(y1.z, p1.z, q1.z); x1[3] = fmaf(y1.w, p1.w, q1.w);
            }
            float s1 = x0[0] + x0[1] + x0[2] + x0[3];
            float s2 = x0[0]*x0[0] + x0[1]*x0[1] + x0[2]*x0[2] + x0[3]*x0[3];
            if (has2) {
                s1 += x1[0] + x1[1] + x1[2] + x1[3];
                s2 += x1[0]*x1[0] + x1[1]*x1[1] + x1[2]*x1[2] + x1[3]*x1[3];
            }
            #pragma unroll
            for (int o = 16; o > 0; o >>= 1) {
                s1 += __shfl_xor_sync(0xffffffffu, s1, o);
                s2 += __shfl_xor_sync(0xffffffffu, s2, o);
            }
            float mean = s1 * (1.0f / Ln);
            float var  = (s2 - (float)Ln * mean * mean) * (1.0f / (Ln - 1));
            float inv  = 1.0f / (sqrtf(fmaxf(var, 0.f)) + 1e-6f);

            float4 o0 = { (x0[0]-mean)*inv, (x0[1]-mean)*inv, (x0[2]-mean)*inv, (x0[3]-mean)*inv };
            orow[ln] = o0;
            if (has2) {
                float4 o1 = { (x1[0]-mean)*inv, (x1[1]-mean)*inv, (x1[2]-mean)*inv, (x1[3]-mean)*inv };
                orow[g2] = o1;
            }
        }
    }
}

// ============================================================================
extern "C" void kernel_launch(void* const* d_in, const int* in_sizes, int n_in,
                              void* d_out, int out_size)
{
    const float* imf  = (const float*)d_in[0];
    const float* txt  = (const float*)d_in[1];
    const float* sam  = (const float*)d_in[2];
    const float* Wsim = (const float*)d_in[3];
    const float* bsim = (const float*)d_in[4];
    float* out = (float*)d_out;

    // dyn = max(phase1 Xw 200*136, phase2 200*104 + 64*104) = 27,456 words
    const int smem = (BWRDS + 64 * WST2) * (int)sizeof(float);   // 109,824 B
    cudaFuncSetAttribute(k_main, cudaFuncAttributeMaxDynamicSharedMemorySize, smem);
    k_main<<<Bn, NT, smem>>>(imf, txt, sam, Wsim, bsim, out);
}

// round 15
// speedup vs baseline: 1.0712x; 1.0463x over previous
#include <cuda_runtime.h>
#include <cuda_bf16.h>
#include <math.h>
#include <stdint.h>

#define Bn 512
#define Cn 256
#define Ln 196
#define Dn 512
#define XWS 132     // phase-1 X word stride: 528B % 128 = 16 -> ldmatrix conflict-free
#define BWS 100     // phase-2 B word stride: 400B % 128 = 16 -> conflict-free
#define AWS 100     // phase-2 A word stride
#define NT 512      // threads per CTA (16 warps) -> 2 CTAs/SM

// raw exp matrix, bf16x2 words: [b][l][98 words]
static __device__ uint32_t g_attnw[(size_t)Bn * Ln * 98];

__device__ __forceinline__ uint32_t smem_u32(const void* p) {
    uint32_t a;
    asm("{ .reg .u64 t; cvta.to.shared.u64 t, %1; cvt.u32.u64 %0, t; }" : "=r"(a) : "l"(p));
    return a;
}
#define LDSM_X4(r0, r1, r2, r3, a) \
    asm volatile("ldmatrix.sync.aligned.m8n8.x4.shared.b16 {%0,%1,%2,%3}, [%4];" \
        : "=r"(r0), "=r"(r1), "=r"(r2), "=r"(r3) : "r"(a))
#define LDSM_X2(r0, r1, a) \
    asm volatile("ldmatrix.sync.aligned.m8n8.x2.shared.b16 {%0,%1}, [%2];" \
        : "=r"(r0), "=r"(r1) : "r"(a))

__device__ __forceinline__ void mma16(float* d, uint32_t a0, uint32_t a1, uint32_t a2,
                                      uint32_t a3, uint32_t b0, uint32_t b1) {
    asm volatile("mma.sync.aligned.m16n8k16.row.col.f32.bf16.bf16.f32 "
        "{%0,%1,%2,%3}, {%4,%5,%6,%7}, {%8,%9}, {%0,%1,%2,%3};"
        : "+f"(d[0]), "+f"(d[1]), "+f"(d[2]), "+f"(d[3])
        : "r"(a0), "r"(a1), "r"(a2), "r"(a3), "r"(b0), "r"(b1));
}
__device__ __forceinline__ void mma8b(float* d, uint32_t a0, uint32_t a1, uint32_t b0) {
    asm volatile("mma.sync.aligned.m16n8k8.row.col.f32.bf16.bf16.f32 "
        "{%0,%1,%2,%3}, {%4,%5}, {%6}, {%0,%1,%2,%3};"
        : "+f"(d[0]), "+f"(d[1]), "+f"(d[2]), "+f"(d[3])
        : "r"(a0), "r"(a1), "r"(b0));
}

// ============================================================================
// Mega-kernel: one CTA per batch, 512 threads (16 warps), 2 CTAs/SM.
// dyn smem: phase1 Xw 208x132 words; phase2 [Bw 200x100][A-slice 64x100].
// ============================================================================
__global__ __launch_bounds__(NT, 2) void k_main(
    const float* __restrict__ imf, const float* __restrict__ txt,
    const float* __restrict__ sam, const float* __restrict__ Wsim,
    const float* __restrict__ bsim, float* __restrict__ out)
{
    extern __shared__ float dyn[];          // 109,824 B
    __shared__ float red[3][16];
    __shared__ float s_simw[200];
    __shared__ __align__(16) float cs1[200];
    __shared__ __align__(16) float cs2[200];
    __shared__ __align__(16) float s_rsum[208];
    __shared__ float s_inv[208];

    int b = blockIdx.x, t = threadIdx.x, w = t >> 5, ln = t & 31;
    int g = ln >> 2, tig = ln & 3;
    const float* Sb = sam + (size_t)b * Cn * Ln;
    uint32_t* Ag = g_attnw + (size_t)b * Ln * 98;

    // ---------------- Phase 0: simw; zero accumulators ----------------
    {
        float* s_imd = dyn;
        float a0 = imf[(size_t)b * Dn + t];
        float c0 = txt[(size_t)b * Dn + t];
        float ni = a0*a0, nt = c0*c0, ct = a0*c0;
        #pragma unroll
        for (int o = 16; o > 0; o >>= 1) {
            ni += __shfl_xor_sync(0xffffffffu, ni, o);
            nt += __shfl_xor_sync(0xffffffffu, nt, o);
            ct += __shfl_xor_sync(0xffffffffu, ct, o);
        }
        if (ln == 0) { red[0][w] = ni; red[1][w] = nt; red[2][w] = ct; }
        if (t < 200) { cs1[t] = 0.f; cs2[t] = 0.f; }
        if (t < 208) { s_inv[t] = 0.f; s_rsum[t] = 0.f; }
        __syncthreads();
        float nI = 0.f, nT = 0.f, cT = 0.f;
        #pragma unroll
        for (int j = 0; j < 16; j++) { nI += red[0][j]; nT += red[1][j]; cT += red[2][j]; }
        float invI = 1.0f / fmaxf(sqrtf(nI), 1e-12f);
        float invT = 1.0f / fmaxf(sqrtf(nT), 1e-12f);
        float cross = cT * invI * invT;
        s_imd[t] = a0 * invI;
        __syncthreads();

        const float4* s4 = reinterpret_cast<const float4*>(s_imd);
        for (int r = w; r < Ln; r += 16) {
            const float4* wr = reinterpret_cast<const float4*>(Wsim + (size_t)r * Dn);
            float acc = 0.f;
            #pragma unroll
            for (int i = 0; i < 4; i++) {
                float4 a = wr[ln + i * 32];
                float4 s = s4[ln + i * 32];
                acc += a.x*s.x + a.y*s.y + a.z*s.z + a.w*s.w;
            }
            #pragma unroll
            for (int o = 16; o > 0; o >>= 1) acc += __shfl_xor_sync(0xffffffffu, acc, o);
            if (ln == 0) {
                acc += bsim[r];
                s_simw[r] = cross * (1.0f / (1.0f + __expf(-acc))) * 0.1f;
            }
        }
    }
    __syncthreads();

    // ---------------- Phase 1: GEMM1 (bf16, ldmatrix) -> exp -> g_attnw -------
    {
        uint32_t* Xw = reinterpret_cast<uint32_t*>(dyn);   // 208 x XWS
        uint32_t Xs = smem_u32(Xw);

        // column norms (coalesced)
        {
            int l = t & 255, ch = t >> 8;
            if (l < Ln) {
                const float* p = Sb + (size_t)(ch * 128) * Ln + l;
                float s0 = 0.f, s1 = 0.f;
                #pragma unroll 8
                for (int c = 0; c < 128; c += 2) {
                    float v0 = p[c * Ln], v1 = p[(c + 1) * Ln];
                    s0 += v0 * v0; s1 += v1 * v1;
                }
                atomicAdd(&s_inv[l], s0 + s1);
            }
        }
        // zero pad rows 196..207
        for (int i = t; i < 12 * XWS; i += NT) Xw[196 * XWS + i] = 0u;
        __syncthreads();
        if (t < Ln) s_inv[t] = 0.25f / fmaxf(sqrtf(s_inv[t]), 1e-12f);
        __syncthreads();

        // stage X[l][c] bf16, scaled (plain layout; lanes sweep c-words -> STS
        // conflict-free; LDG strided but L2-hot)
        for (int idx = t; idx < 49 * 128; idx += NT) {
            int l4 = idx >> 7, c2 = idx & 127;
            int l0 = l4 * 4;
            float4 v0 = *reinterpret_cast<const float4*>(Sb + (size_t)(2*c2)   * Ln + l0);
            float4 v1 = *reinterpret_cast<const float4*>(Sb + (size_t)(2*c2+1) * Ln + l0);
            float i0 = s_inv[l0], i1 = s_inv[l0+1], i2 = s_inv[l0+2], i3 = s_inv[l0+3];
            __nv_bfloat162 h0 = __floats2bfloat162_rn(v0.x * i0, v1.x * i0);
            __nv_bfloat162 h1 = __floats2bfloat162_rn(v0.y * i1, v1.y * i1);
            __nv_bfloat162 h2 = __floats2bfloat162_rn(v0.z * i2, v1.z * i2);
            __nv_bfloat162 h3 = __floats2bfloat162_rn(v0.w * i3, v1.w * i3);
            Xw[(l0+0) * XWS + c2] = *reinterpret_cast<uint32_t*>(&h0);
            Xw[(l0+1) * XWS + c2] = *reinterpret_cast<uint32_t*>(&h1);
            Xw[(l0+2) * XWS + c2] = *reinterpret_cast<uint32_t*>(&h2);
            Xw[(l0+3) * XWS + c2] = *reinterpret_cast<uint32_t*>(&h3);
        }
        __syncthreads();

        // ldmatrix lane roles
        int rApat = (ln & 7) + ((ln >> 3) & 1) * 8;   // A x4 row pattern
        int khA   = ln >> 4;                          // A x4 k-half
        int rBpat = (ln & 7) + (ln >> 4) * 8;         // B x4 row pattern
        int khBp  = (ln >> 3) & 1;                    // B x4 k-half
        int l15   = ln & 15;
        int rB2   = l15 & 7;                          // B x2 row pattern
        int khB2  = l15 >> 3;

        // 64 jobs: job<4 -> mt0 slices (7,6,6,6); else mt 1..12 x 5 slices of 5
        for (int r = 0; r < 4; r++) {
            int job = r * 16 + w;
            int mt, cb, nfr;
            if (job < 4) {
                mt = 0;
                nfr = (job == 0) ? 7 : 6;
                cb  = (job == 0) ? 0 : (56 + (job - 1) * 48);
            } else {
                int j = job - 4;
                mt = 1 + j / 5;
                cb = (j % 5) * 40;
                nfr = 5;
            }

            float acc[7][4];
            #pragma unroll
            for (int n = 0; n < 7; n++)
                #pragma unroll
                for (int j2 = 0; j2 < 4; j2++) acc[n][j2] = 0.f;

            uint32_t aad = Xs + (((mt * 16 + rApat) * XWS) + khA * 4) * 4;
            uint32_t bad[4];
            #pragma unroll
            for (int fp = 0; fp < 4; fp++) {
                bool full = (fp * 2 + 1 < nfr);
                int rb = cb + fp * 16 + (full ? rBpat : rB2);
                int kh = full ? khBp : khB2;
                bad[fp] = Xs + ((rb * XWS) + kh * 4) * 4;
            }

            #pragma unroll 4
            for (int ks = 0; ks < 16; ks++) {
                uint32_t a0, a1, a2, a3;
                LDSM_X4(a0, a1, a2, a3, aad); aad += 32;
                #pragma unroll
                for (int fp = 0; fp < 4; fp++) {
                    if (fp * 2 < nfr) {
                        if (fp * 2 + 1 < nfr) {
                            uint32_t b0, b1, b2, b3;
                            LDSM_X4(b0, b1, b2, b3, bad[fp]);
                            mma16(acc[2*fp],   a0, a1, a2, a3, b0, b1);
                            mma16(acc[2*fp+1], a0, a1, a2, a3, b2, b3);
                        } else {
                            uint32_t b0, b1;
                            LDSM_X2(b0, b1, bad[fp]);
                            mma16(acc[2*fp], a0, a1, a2, a3, b0, b1);
                        }
                        bad[fp] += 32;
                    }
                }
            }

            // epilogue: exp -> row sums + bf16x2 store to g_attnw row l
            #pragma unroll
            for (int rh = 0; rh < 2; rh++) {
                int l = mt * 16 + g + 8 * rh;
                float e[7][2];
                float sum = 0.f;
                #pragma unroll
                for (int n = 0; n < 7; n++) {
                    if (n < nfr) {
                        int col0 = cb + n * 8 + 2 * tig;
                        float e0 = __expf(acc[n][rh*2]);
                        float e1 = __expf(acc[n][rh*2+1]);
                        e[n][0] = e0; e[n][1] = e1;
                        if (col0 < Ln) sum += e0 + e1;
                    }
                }
                sum += __shfl_xor_sync(0xffffffffu, sum, 1);
                sum += __shfl_xor_sync(0xffffffffu, sum, 2);
                if (l < Ln) {
                    if (tig == 0) atomicAdd(&s_rsum[l], sum);
                    uint32_t* arow = Ag + (size_t)l * 98;
                    #pragma unroll
                    for (int n = 0; n < 7; n++) {
                        if (n < nfr) {
                            int col0 = cb + n * 8 + 2 * tig;
                            if (col0 < Ln) {
                                __nv_bfloat162 h = __floats2bfloat162_rn(e[n][0], e[n][1]);
                                arow[col0 >> 1] = *reinterpret_cast<uint32_t*>(&h);
                            }
                        }
                    }
                }
            }
        }
    }
    __syncthreads();
    if (t < Ln) s_rsum[t] = 1.0f / s_rsum[t];
    __syncthreads();

    // ---------------- Phase 2: GEMM2 (bf16, ldmatrix); B resident -------------
    {
        uint32_t* Bw = reinterpret_cast<uint32_t*>(dyn);             // 200 x 100
        uint32_t* Aw = reinterpret_cast<uint32_t*>(dyn) + 200 * BWS; // 64 x 100
        uint32_t Bs = smem_u32(Bw);
        uint32_t As = smem_u32(Aw);

        // stage B[m][w2] from g_attnw (plain; rows>=196 and words 98,99 zero)
        {
            int m = t / 50, p2 = t - m * 50;      // 512 = 10*50 + 12
            for (int idx = t; idx < 200 * 50; idx += NT) {
                int w2 = 2 * p2;
                uint2 v = make_uint2(0u, 0u);
                if (m < Ln && w2 < 98)
                    v = *reinterpret_cast<const uint2*>(g_attnw + ((size_t)b * Ln + m) * 98 + w2);
                Bw[m * BWS + w2]     = v.x;
                Bw[m * BWS + w2 + 1] = v.y;
                p2 += 12; m += 10;
                if (p2 >= 50) { p2 -= 50; m += 1; }
            }
        }

        int rApat = (ln & 7) + ((ln >> 3) & 1) * 8;
        int khA   = ln >> 4;
        int rBpat = (ln & 7) + (ln >> 4) * 8;
        int khBp  = (ln >> 3) & 1;
        int l15   = ln & 15;
        int rB2   = l15 & 7;
        int khB2  = l15 >> 3;

        for (int r = 0; r < 4; r++) {
            __syncthreads();
            // stage A slice rows [64r, 64r+64): A'[c][l] = bf16(sam[c][l]*rsum[l])
            {
                int cl = t / 25, g4 = t - cl * 25;   // 512 = 20*25 + 12
                for (int idx = t; idx < 64 * 25; idx += NT) {
                    int c = 64 * r + cl;
                    int l0 = g4 * 8;
                    float4 va = make_float4(0.f, 0.f, 0.f, 0.f);
                    float4 vb = make_float4(0.f, 0.f, 0.f, 0.f);
                    const float* src = Sb + (size_t)c * Ln + l0;
                    va = *reinterpret_cast<const float4*>(src);          // l0 <= 192 < 196
                    if (l0 + 4 < Ln) vb = *reinterpret_cast<const float4*>(src + 4);
                    float4 r0 = *reinterpret_cast<const float4*>(s_rsum + l0);
                    float4 r1 = *reinterpret_cast<const float4*>(s_rsum + l0 + 4);
                    __nv_bfloat162 h0 = __floats2bfloat162_rn(va.x * r0.x, va.y * r0.y);
                    __nv_bfloat162 h1 = __floats2bfloat162_rn(va.z * r0.z, va.w * r0.w);
                    __nv_bfloat162 h2 = __floats2bfloat162_rn(vb.x * r1.x, vb.y * r1.y);
                    __nv_bfloat162 h3 = __floats2bfloat162_rn(vb.z * r1.z, vb.w * r1.w);
                    uint32_t* dst = Aw + cl * AWS;
                    int w2 = g4 * 4;
                    dst[w2]     = *reinterpret_cast<uint32_t*>(&h0);
                    dst[w2 + 1] = *reinterpret_cast<uint32_t*>(&h1);
                    dst[w2 + 2] = *reinterpret_cast<uint32_t*>(&h2);
                    dst[w2 + 3] = *reinterpret_cast<uint32_t*>(&h3);
                    g4 += 12; cl += 20;
                    if (g4 >= 25) { g4 -= 25; cl += 1; }
                }
            }
            __syncthreads();

            int q = (r + w) & 3;
            int mtl = (w >> 2);
            int mtg = 4 * r + mtl;
            int cbm = (q == 0) ? 0 : (q == 1) ? 56 : (q == 2) ? 104 : 160;
            int nfr = (q == 0 || q == 2) ? 7 : (q == 1) ? 6 : 5;

            float acc[7][4];
            #pragma unroll
            for (int n = 0; n < 7; n++)
                #pragma unroll
                for (int j = 0; j < 4; j++) acc[n][j] = 0.f;

            uint32_t aad = As + (((mtl * 16 + rApat) * AWS) + khA * 4) * 4;
            uint32_t bad[4];
            #pragma unroll
            for (int fp = 0; fp < 4; fp++) {
                bool full = (fp * 2 + 1 < nfr);
                int rb = cbm + fp * 16 + (full ? rBpat : rB2);
                int kh = full ? khBp : khB2;
                bad[fp] = Bs + ((rb * BWS) + kh * 4) * 4;
            }

            #pragma unroll 4
            for (int ks = 0; ks < 12; ks++) {
                uint32_t a0, a1, a2, a3;
                LDSM_X4(a0, a1, a2, a3, aad); aad += 32;
                #pragma unroll
                for (int fp = 0; fp < 4; fp++) {
                    if (fp * 2 < nfr) {
                        if (fp * 2 + 1 < nfr) {
                            uint32_t b0, b1, b2, b3;
                            LDSM_X4(b0, b1, b2, b3, bad[fp]);
                            mma16(acc[2*fp],   a0, a1, a2, a3, b0, b1);
                            mma16(acc[2*fp+1], a0, a1, a2, a3, b2, b3);
                        } else {
                            uint32_t b0, b1;
                            LDSM_X2(b0, b1, bad[fp]);
                            mma16(acc[2*fp], a0, a1, a2, a3, b0, b1);
                        }
                        bad[fp] += 32;
                    }
                }
            }
            // k8 tail (k = 192..199; elements 196..199 are zero pads)
            {
                uint32_t a0, a1;
                LDSM_X2(a0, a1, As + (((mtl * 16 + l15) * AWS) + 96) * 4);
                uint32_t c0, c1, c2, c3, d0, d1, d2, d3;
                LDSM_X4(c0, c1, c2, c3, Bs + (((cbm + ln) * BWS) + 96) * 4);
                LDSM_X4(d0, d1, d2, d3, Bs + (((cbm + 32 + ln) * BWS) + 96) * 4);
                mma8b(acc[0], a0, a1, c0);
                mma8b(acc[1], a0, a1, c1);
                mma8b(acc[2], a0, a1, c2);
                mma8b(acc[3], a0, a1, c3);
                mma8b(acc[4], a0, a1, d0);
                if (nfr > 5) mma8b(acc[5], a0, a1, d1);
                if (nfr > 6) mma8b(acc[6], a0, a1, d2);
            }

            // epilogue: y = sam + D -> out
            int c0r = mtg * 16 + g;
            int c1r = c0r + 8;
            const float* S0 = Sb + (size_t)c0r * Ln;
            const float* S1 = Sb + (size_t)c1r * Ln;
            float* O0 = out + ((size_t)b * Cn + c0r) * Ln;
            float* O1 = out + ((size_t)b * Cn + c1r) * Ln;
            #pragma unroll
            for (int n = 0; n < 7; n++) {
                if (n < nfr) {
                    int col0 = cbm + n * 8 + 2 * tig;
                    if (col0 < Ln) {
                        float2 s0 = *reinterpret_cast<const float2*>(S0 + col0);
                        float2 s1 = *reinterpret_cast<const float2*>(S1 + col0);
                        *reinterpret_cast<float2*>(O0 + col0) =
                            make_float2(s0.x + acc[n][0], s0.y + acc[n][1]);
                        *reinterpret_cast<float2*>(O1 + col0) =
                            make_float2(s1.x + acc[n][2], s1.y + acc[n][3]);
                    }
                }
            }
        }
    }
    __syncthreads();

    // ---------------- Phase 2b: column stats from out (L2-hot, coalesced) ------
    {
        int l = t & 255, ch = t >> 8;
        if (l < Ln) {
            const float* p = out + (size_t)b * Cn * Ln + (size_t)(ch * 128) * Ln + l;
            float s1 = 0.f, s2 = 0.f;
            #pragma unroll 8
            for (int c = 0; c < 128; c += 2) {
                float v0 = p[c * Ln], v1 = p[(c + 1) * Ln];
                s1 += v0 + v1;
                s2 += v0 * v0 + v1 * v1;
            }
            atomicAdd(&cs1[l], s1);
            atomicAdd(&cs2[l], s2);
        }
    }
    __syncthreads();

    // ---------------- Phase 3: channel-LN affine P,Q ----------------
    if (t < Ln) {
        float a = 0.5f * s_simw[t];
        float mu_y  = cs1[t] * (1.0f / Cn);
        float var_y = cs2[t] * (1.0f / Cn) - mu_y * mu_y;
        float inv_s = rsqrtf(a * a * var_y + 1e-5f);
        cs1[t] = a * inv_s;
        cs2[t] = -a * mu_y * inv_s;
    }
    if (t >= Ln && t < 200) { cs1[t] = 0.f; cs2[t] = 0.f; }
    __syncthreads();

    // ---------------- Phase 4: spatial standardization (out L2-hot) ----------
    {
        const float4* P4 = reinterpret_cast<const float4*>(cs1);
        const float4* Q4 = reinterpret_cast<const float4*>(cs2);
        bool has2 = (ln + 32) < Ln / 4;
        int g2 = has2 ? (ln + 32) : 0;
        float4 p0 = P4[ln], q0 = Q4[ln];
        float4 p1 = P4[g2], q1 = Q4[g2];

        for (int c = w; c < Cn; c += 16) {
            float4* orow = reinterpret_cast<float4*>(out + ((size_t)b * Cn + c) * Ln);
            float4 y0 = orow[ln];
            float x0[4] = { fmaf(y0.x, p0.x, q0.x), fmaf(y0.y, p0.y, q0.y),
                            fmaf(y0.z, p0.z, q0.z), fmaf(y0.w, p0.w, q0.w) };
            float x1[4] = { 0.f, 0.f, 0.f, 0.f };
            if (has2) {
                float4 y1 = orow[g2];
                x1[0] = fmaf(y1.x, p1.x, q1.x); x1[1] = fmaf(y1.y, p1.y, q1.y);
                x1[2] = fmaf(y1.z, p1.z, q1.z); x1[3] = fmaf(y1.w, p1.w, q1.w);
            }
            float s1 = x0[0] + x0[1] + x0[2] + x0[3];
            float s2 = x0[0]*x0[0] + x0[1]*x0[1] + x0[2]*x0[2] + x0[3]*x0[3];
            if (has2) {
                s1 += x1[0] + x1[1] + x1[2] + x1[3];
                s2 += x1[0]*x1[0] + x1[1]*x1[1] + x1[2]*x1[2] + x1[3]*x1[3];
            }
            #pragma unroll
            for (int o = 16; o > 0; o >>= 1) {
                s1 += __shfl_xor_sync(0xffffffffu, s1, o);
                s2 += __shfl_xor_sync(0xffffffffu, s2, o);
            }
            float mean = s1 * (1.0f / Ln);
            float var  = (s2 - (float)Ln * mean * mean) * (1.0f / (Ln - 1));
            float inv  = 1.0f / (sqrtf(fmaxf(var, 0.f)) + 1e-6f);

            float4 o0 = { (x0[0]-mean)*inv, (x0[1]-mean)*inv, (x0[2]-mean)*inv, (x0[3]-mean)*inv };
            orow[ln] = o0;
            if (has2) {
                float4 o1 = { (x1[0]-mean)*inv, (x1[1]-mean)*inv, (x1[2]-mean)*inv, (x1[3]-mean)*inv };
                orow[g2] = o1;
            }
        }
    }
}

// ============================================================================
extern "C" void kernel_launch(void* const* d_in, const int* in_sizes, int n_in,
                              void* d_out, int out_size)
{
    const float* imf  = (const float*)d_in[0];
    const float* txt  = (const float*)d_in[1];
    const float* sam  = (const float*)d_in[2];
    const float* Wsim = (const float*)d_in[3];
    const float* bsim = (const float*)d_in[4];
    float* out = (float*)d_out;

    // dyn = max(phase1 208*132, phase2 200*100 + 64*100) = 27,456 words
    const int smem = 208 * XWS * (int)sizeof(float);   // 109,824 B
    cudaFuncSetAttribute(k_main, cudaFuncAttributeMaxDynamicSharedMemorySize, smem);
    k_main<<<Bn, NT, smem>>>(imf, txt, sam, Wsim, bsim, out);
}

// round 16
// speedup vs baseline: 1.1746x; 1.0965x over previous
#include <cuda_runtime.h>
#include <cuda_bf16.h>
#include <math.h>
#include <stdint.h>

#define Bn 512
#define Cn 256
#define Ln 196
#define Dn 512
#define XWS 100     // phase-1 X word stride ([c][l] natural): 400B % 128 = 16
#define BWS 100     // phase-2 B word stride
#define AWS 100     // phase-2 A word stride
#define NT 512      // threads per CTA (16 warps) -> 2 CTAs/SM

// raw exp matrix, bf16x2 words: [b][l][98 words]
static __device__ uint32_t g_attnw[(size_t)Bn * Ln * 98];

__device__ __forceinline__ uint32_t smem_u32(const void* p) {
    uint32_t a;
    asm("{ .reg .u64 t; cvta.to.shared.u64 t, %1; cvt.u32.u64 %0, t; }" : "=r"(a) : "l"(p));
    return a;
}
#define LDSM_X4(r0, r1, r2, r3, a) \
    asm volatile("ldmatrix.sync.aligned.m8n8.x4.shared.b16 {%0,%1,%2,%3}, [%4];" \
        : "=r"(r0), "=r"(r1), "=r"(r2), "=r"(r3) : "r"(a))
#define LDSM_X2(r0, r1, a) \
    asm volatile("ldmatrix.sync.aligned.m8n8.x2.shared.b16 {%0,%1}, [%2];" \
        : "=r"(r0), "=r"(r1) : "r"(a))
#define LDSM_X4T(r0, r1, r2, r3, a) \
    asm volatile("ldmatrix.sync.aligned.m8n8.x4.trans.shared.b16 {%0,%1,%2,%3}, [%4];" \
        : "=r"(r0), "=r"(r1), "=r"(r2), "=r"(r3) : "r"(a))
#define LDSM_X2T(r0, r1, a) \
    asm volatile("ldmatrix.sync.aligned.m8n8.x2.trans.shared.b16 {%0,%1}, [%2];" \
        : "=r"(r0), "=r"(r1) : "r"(a))

__device__ __forceinline__ void mma16(float* d, uint32_t a0, uint32_t a1, uint32_t a2,
                                      uint32_t a3, uint32_t b0, uint32_t b1) {
    asm volatile("mma.sync.aligned.m16n8k16.row.col.f32.bf16.bf16.f32 "
        "{%0,%1,%2,%3}, {%4,%5,%6,%7}, {%8,%9}, {%0,%1,%2,%3};"
        : "+f"(d[0]), "+f"(d[1]), "+f"(d[2]), "+f"(d[3])
        : "r"(a0), "r"(a1), "r"(a2), "r"(a3), "r"(b0), "r"(b1));
}
__device__ __forceinline__ void mma8b(float* d, uint32_t a0, uint32_t a1, uint32_t b0) {
    asm volatile("mma.sync.aligned.m16n8k8.row.col.f32.bf16.bf16.f32 "
        "{%0,%1,%2,%3}, {%4,%5}, {%6}, {%0,%1,%2,%3};"
        : "+f"(d[0]), "+f"(d[1]), "+f"(d[2]), "+f"(d[3])
        : "r"(a0), "r"(a1), "r"(b0));
}

// ============================================================================
// Mega-kernel: one CTA per batch, 512 threads (16 warps), 2 CTAs/SM.
// dyn smem: phase1 Xn 256x100 words ([c][l], ldmatrix.trans);
//           phase2 [Bw 200x100][A-slice 64x100].
// ============================================================================
__global__ __launch_bounds__(NT, 2) void k_main(
    const float* __restrict__ imf, const float* __restrict__ txt,
    const float* __restrict__ sam, const float* __restrict__ Wsim,
    const float* __restrict__ bsim, float* __restrict__ out)
{
    extern __shared__ float dyn[];          // 105,600 B
    __shared__ float red[3][16];
    __shared__ float s_simw[200];
    __shared__ __align__(16) float cs1[200];
    __shared__ __align__(16) float cs2[200];
    __shared__ __align__(16) float s_rsum[208];
    __shared__ float s_inv[208];

    int b = blockIdx.x, t = threadIdx.x, w = t >> 5, ln = t & 31;
    int g = ln >> 2, tig = ln & 3;
    const float* Sb = sam + (size_t)b * Cn * Ln;
    uint32_t* Ag = g_attnw + (size_t)b * Ln * 98;

    // ---------------- Phase 0: simw; zero accumulators ----------------
    {
        float* s_imd = dyn;
        float a0 = imf[(size_t)b * Dn + t];
        float c0 = txt[(size_t)b * Dn + t];
        float ni = a0*a0, nt = c0*c0, ct = a0*c0;
        #pragma unroll
        for (int o = 16; o > 0; o >>= 1) {
            ni += __shfl_xor_sync(0xffffffffu, ni, o);
            nt += __shfl_xor_sync(0xffffffffu, nt, o);
            ct += __shfl_xor_sync(0xffffffffu, ct, o);
        }
        if (ln == 0) { red[0][w] = ni; red[1][w] = nt; red[2][w] = ct; }
        if (t < 200) { cs1[t] = 0.f; cs2[t] = 0.f; }
        if (t < 208) { s_inv[t] = 0.f; s_rsum[t] = 0.f; }
        __syncthreads();
        float nI = 0.f, nT = 0.f, cT = 0.f;
        #pragma unroll
        for (int j = 0; j < 16; j++) { nI += red[0][j]; nT += red[1][j]; cT += red[2][j]; }
        float invI = 1.0f / fmaxf(sqrtf(nI), 1e-12f);
        float invT = 1.0f / fmaxf(sqrtf(nT), 1e-12f);
        float cross = cT * invI * invT;
        s_imd[t] = a0 * invI;
        __syncthreads();

        const float4* s4 = reinterpret_cast<const float4*>(s_imd);
        for (int r = w; r < Ln; r += 16) {
            const float4* wr = reinterpret_cast<const float4*>(Wsim + (size_t)r * Dn);
            float acc = 0.f;
            #pragma unroll
            for (int i = 0; i < 4; i++) {
                float4 a = wr[ln + i * 32];
                float4 s = s4[ln + i * 32];
                acc += a.x*s.x + a.y*s.y + a.z*s.z + a.w*s.w;
            }
            #pragma unroll
            for (int o = 16; o > 0; o >>= 1) acc += __shfl_xor_sync(0xffffffffu, acc, o);
            if (ln == 0) {
                acc += bsim[r];
                s_simw[r] = cross * (1.0f / (1.0f + __expf(-acc))) * 0.1f;
            }
        }
    }
    __syncthreads();

    // ---------------- Phase 1: GEMM1 (bf16, ldmatrix.trans) -> exp -> g_attnw --
    {
        uint32_t* Xn = reinterpret_cast<uint32_t*>(dyn);   // 256 x XWS  ([c][l])
        uint32_t Xs = smem_u32(Xn);

        // column norms (coalesced along l)
        {
            int l = t & 255, ch = t >> 8;
            if (l < Ln) {
                const float* p = Sb + (size_t)(ch * 128) * Ln + l;
                float s0 = 0.f, s1 = 0.f;
                #pragma unroll 8
                for (int c = 0; c < 128; c += 2) {
                    float v0 = p[c * Ln], v1 = p[(c + 1) * Ln];
                    s0 += v0 * v0; s1 += v1 * v1;
                }
                atomicAdd(&s_inv[l], s0 + s1);
            }
        }
        // zero pad words 98,99 of every row
        {
            int c = t >> 1;
            Xn[c * XWS + 98 + (t & 1)] = 0u;
        }
        __syncthreads();
        if (t < Ln) s_inv[t] = 0.25f / fmaxf(sqrtf(s_inv[t]), 1e-12f);
        __syncthreads();

        // stage Xn[c][l] = bf16(sam[c][l] * inv[l]) -- fully coalesced
        {
            int c = t / 25, g4 = t - c * 25;   // 512 = 20*25 + 12
            for (int idx = t; idx < 256 * 25; idx += NT) {
                int l0 = g4 * 8;
                float4 va, vb = make_float4(0.f, 0.f, 0.f, 0.f);
                const float* src = Sb + (size_t)c * Ln + l0;
                va = *reinterpret_cast<const float4*>(src);        // l0 <= 192 < 196
                if (l0 + 4 < Ln) vb = *reinterpret_cast<const float4*>(src + 4);
                float4 r0 = *reinterpret_cast<const float4*>(s_inv + l0);
                float4 r1 = *reinterpret_cast<const float4*>(s_inv + l0 + 4);
                __nv_bfloat162 h0 = __floats2bfloat162_rn(va.x * r0.x, va.y * r0.y);
                __nv_bfloat162 h1 = __floats2bfloat162_rn(va.z * r0.z, va.w * r0.w);
                __nv_bfloat162 h2 = __floats2bfloat162_rn(vb.x * r1.x, vb.y * r1.y);
                __nv_bfloat162 h3 = __floats2bfloat162_rn(vb.z * r1.z, vb.w * r1.w);
                uint32_t* dst = Xn + c * XWS;
                int w2 = g4 * 4;
                dst[w2]     = *reinterpret_cast<uint32_t*>(&h0);
                dst[w2 + 1] = *reinterpret_cast<uint32_t*>(&h1);
                dst[w2 + 2] = *reinterpret_cast<uint32_t*>(&h2);
                dst[w2 + 3] = *reinterpret_cast<uint32_t*>(&h3);
                g4 += 12; c += 20;
                if (g4 >= 25) { g4 -= 25; c += 1; }
            }
        }
        __syncthreads();

        // trans lane roles
        int rAT  = (ln & 7) + (ln >> 4) * 8;          // A: k-row pattern
        int aCol = ((ln >> 3) & 1) * 4;               // A: +8 m -> +4 words
        int rBT  = (ln & 7) + ((ln >> 3) & 1) * 8;    // B x4: k-row pattern
        int bCol = (ln >> 4) * 4;                     // B x4: +8 n -> +4 words
        int rB2T = ln & 15;                           // B x2: k rows 0..15

        // 64 jobs: job<4 -> mt0 slices (7,6,6,6); else mt 1..12 x 5 slices of 5
        for (int r = 0; r < 4; r++) {
            int job = r * 16 + w;
            int mt, cb, nfr;
            if (job < 4) {
                mt = 0;
                nfr = (job == 0) ? 7 : 6;
                cb  = (job == 0) ? 0 : (56 + (job - 1) * 48);
            } else {
                int j = job - 4;
                mt = 1 + j / 5;
                cb = (j % 5) * 40;
                nfr = 5;
            }

            float acc[7][4];
            #pragma unroll
            for (int n = 0; n < 7; n++)
                #pragma unroll
                for (int j2 = 0; j2 < 4; j2++) acc[n][j2] = 0.f;

            uint32_t aad = Xs + ((rAT * XWS) + mt * 8 + aCol) * 4;
            uint32_t bad[4];
            #pragma unroll
            for (int fp = 0; fp < 4; fp++) {
                bool full = (fp * 2 + 1 < nfr);
                int rk = full ? rBT : rB2T;
                int cw = (cb >> 1) + fp * 8 + (full ? bCol : 0);
                bad[fp] = Xs + ((rk * XWS) + cw) * 4;
            }

            #pragma unroll 4
            for (int ks = 0; ks < 16; ks++) {
                uint32_t a0, a1, a2, a3;
                LDSM_X4T(a0, a1, a2, a3, aad); aad += 16 * XWS * 4;
                #pragma unroll
                for (int fp = 0; fp < 4; fp++) {
                    if (fp * 2 < nfr) {
                        if (fp * 2 + 1 < nfr) {
                            uint32_t b0, b1, b2, b3;
                            LDSM_X4T(b0, b1, b2, b3, bad[fp]);
                            mma16(acc[2*fp],   a0, a1, a2, a3, b0, b1);
                            mma16(acc[2*fp+1], a0, a1, a2, a3, b2, b3);
                        } else {
                            uint32_t b0, b1;
                            LDSM_X2T(b0, b1, bad[fp]);
                            mma16(acc[2*fp], a0, a1, a2, a3, b0, b1);
                        }
                        bad[fp] += 16 * XWS * 4;
                    }
                }
            }

            // epilogue: exp -> row sums + bf16x2 store to g_attnw row l
            #pragma unroll
            for (int rh = 0; rh < 2; rh++) {
                int l = mt * 16 + g + 8 * rh;
                float e[7][2];
                float sum = 0.f;
                #pragma unroll
                for (int n = 0; n < 7; n++) {
                    if (n < nfr) {
                        int col0 = cb + n * 8 + 2 * tig;
                        float e0 = __expf(acc[n][rh*2]);
                        float e1 = __expf(acc[n][rh*2+1]);
                        e[n][0] = e0; e[n][1] = e1;
                        if (col0 < Ln) sum += e0 + e1;
                    }
                }
                sum += __shfl_xor_sync(0xffffffffu, sum, 1);
                sum += __shfl_xor_sync(0xffffffffu, sum, 2);
                if (l < Ln) {
                    if (tig == 0) atomicAdd(&s_rsum[l], sum);
                    uint32_t* arow = Ag + (size_t)l * 98;
                    #pragma unroll
                    for (int n = 0; n < 7; n++) {
                        if (n < nfr) {
                            int col0 = cb + n * 8 + 2 * tig;
                            if (col0 < Ln) {
                                __nv_bfloat162 h = __floats2bfloat162_rn(e[n][0], e[n][1]);
                                arow[col0 >> 1] = *reinterpret_cast<uint32_t*>(&h);
                            }
                        }
                    }
                }
            }
        }
    }
    __syncthreads();
    if (t < Ln) s_rsum[t] = 1.0f / s_rsum[t];
    __syncthreads();

    // ---------------- Phase 2: GEMM2 (bf16, ldmatrix); B resident -------------
    {
        uint32_t* Bw = reinterpret_cast<uint32_t*>(dyn);             // 200 x 100
        uint32_t* Aw = reinterpret_cast<uint32_t*>(dyn) + 200 * BWS; // 64 x 100
        uint32_t Bs = smem_u32(Bw);
        uint32_t As = smem_u32(Aw);

        // stage B[m][w2] from g_attnw (rows>=196 and words 98,99 zero)
        {
            int m = t / 50, p2 = t - m * 50;      // 512 = 10*50 + 12
            for (int idx = t; idx < 200 * 50; idx += NT) {
                int w2 = 2 * p2;
                uint2 v = make_uint2(0u, 0u);
                if (m < Ln && w2 < 98)
                    v = *reinterpret_cast<const uint2*>(g_attnw + ((size_t)b * Ln + m) * 98 + w2);
                Bw[m * BWS + w2]     = v.x;
                Bw[m * BWS + w2 + 1] = v.y;
                p2 += 12; m += 10;
                if (p2 >= 50) { p2 -= 50; m += 1; }
            }
        }

        int rApat = (ln & 7) + ((ln >> 3) & 1) * 8;
        int khA   = ln >> 4;
        int rBpat = (ln & 7) + (ln >> 4) * 8;
        int khBp  = (ln >> 3) & 1;
        int l15   = ln & 15;
        int rB2   = l15 & 7;
        int khB2  = l15 >> 3;

        for (int r = 0; r < 4; r++) {
            __syncthreads();
            // stage A slice rows [64r, 64r+64): A'[c][l] = bf16(sam[c][l]*rsum[l])
            {
                int cl = t / 25, g4 = t - cl * 25;   // 512 = 20*25 + 12
                for (int idx = t; idx < 64 * 25; idx += NT) {
                    int c = 64 * r + cl;
                    int l0 = g4 * 8;
                    float4 va, vb = make_float4(0.f, 0.f, 0.f, 0.f);
                    const float* src = Sb + (size_t)c * Ln + l0;
                    va = *reinterpret_cast<const float4*>(src);
                    if (l0 + 4 < Ln) vb = *reinterpret_cast<const float4*>(src + 4);
                    float4 r0 = *reinterpret_cast<const float4*>(s_rsum + l0);
                    float4 r1 = *reinterpret_cast<const float4*>(s_rsum + l0 + 4);
                    __nv_bfloat162 h0 = __floats2bfloat162_rn(va.x * r0.x, va.y * r0.y);
                    __nv_bfloat162 h1 = __floats2bfloat162_rn(va.z * r0.z, va.w * r0.w);
                    __nv_bfloat162 h2 = __floats2bfloat162_rn(vb.x * r1.x, vb.y * r1.y);
                    __nv_bfloat162 h3 = __floats2bfloat162_rn(vb.z * r1.z, vb.w * r1.w);
                    uint32_t* dst = Aw + cl * AWS;
                    int w2 = g4 * 4;
                    dst[w2]     = *reinterpret_cast<uint32_t*>(&h0);
                    dst[w2 + 1] = *reinterpret_cast<uint32_t*>(&h1);
                    dst[w2 + 2] = *reinterpret_cast<uint32_t*>(&h2);
                    dst[w2 + 3] = *reinterpret_cast<uint32_t*>(&h3);
                    g4 += 12; cl += 20;
                    if (g4 >= 25) { g4 -= 25; cl += 1; }
                }
            }
            __syncthreads();

            int q = (r + w) & 3;
            int mtl = (w >> 2);
            int mtg = 4 * r + mtl;
            int cbm = (q == 0) ? 0 : (q == 1) ? 56 : (q == 2) ? 104 : 160;
            int nfr = (q == 0 || q == 2) ? 7 : (q == 1) ? 6 : 5;

            float acc[7][4];
            #pragma unroll
            for (int n = 0; n < 7; n++)
                #pragma unroll
                for (int j = 0; j < 4; j++) acc[n][j] = 0.f;

            uint32_t aad = As + (((mtl * 16 + rApat) * AWS) + khA * 4) * 4;
            uint32_t bad[4];
            #pragma unroll
            for (int fp = 0; fp < 4; fp++) {
                bool full = (fp * 2 + 1 < nfr);
                int rb = cbm + fp * 16 + (full ? rBpat : rB2);
                int kh = full ? khBp : khB2;
                bad[fp] = Bs + ((rb * BWS) + kh * 4) * 4;
            }

            #pragma unroll 4
            for (int ks = 0; ks < 12; ks++) {
                uint32_t a0, a1, a2, a3;
                LDSM_X4(a0, a1, a2, a3, aad); aad += 32;
                #pragma unroll
                for (int fp = 0; fp < 4; fp++) {
                    if (fp * 2 < nfr) {
                        if (fp * 2 + 1 < nfr) {
                            uint32_t b0, b1, b2, b3;
                            LDSM_X4(b0, b1, b2, b3, bad[fp]);
                            mma16(acc[2*fp],   a0, a1, a2, a3, b0, b1);
                            mma16(acc[2*fp+1], a0, a1, a2, a3, b2, b3);
                        } else {
                            uint32_t b0, b1;
                            LDSM_X2(b0, b1, bad[fp]);
                            mma16(acc[2*fp], a0, a1, a2, a3, b0, b1);
                        }
                        bad[fp] += 32;
                    }
                }
            }
            // k8 tail (k = 192..199; elements 196..199 are zero pads)
            {
                uint32_t a0, a1;
                LDSM_X2(a0, a1, As + (((mtl * 16 + l15) * AWS) + 96) * 4);
                uint32_t c0, c1, c2, c3, d0, d1, d2, d3;
                LDSM_X4(c0, c1, c2, c3, Bs + (((cbm + ln) * BWS) + 96) * 4);
                LDSM_X4(d0, d1, d2, d3, Bs + (((cbm + 32 + ln) * BWS) + 96) * 4);
                mma8b(acc[0], a0, a1, c0);
                mma8b(acc[1], a0, a1, c1);
                mma8b(acc[2], a0, a1, c2);
                mma8b(acc[3], a0, a1, c3);
                mma8b(acc[4], a0, a1, d0);
                if (nfr > 5) mma8b(acc[5], a0, a1, d1);
                if (nfr > 6) mma8b(acc[6], a0, a1, d2);
            }

            // epilogue: y = sam + D -> out
            int c0r = mtg * 16 + g;
            int c1r = c0r + 8;
            const float* S0 = Sb + (size_t)c0r * Ln;
            const float* S1 = Sb + (size_t)c1r * Ln;
            float* O0 = out + ((size_t)b * Cn + c0r) * Ln;
            float* O1 = out + ((size_t)b * Cn + c1r) * Ln;
            #pragma unroll
            for (int n = 0; n < 7; n++) {
                if (n < nfr) {
                    int col0 = cbm + n * 8 + 2 * tig;
                    if (col0 < Ln) {
                        float2 s0 = *reinterpret_cast<const float2*>(S0 + col0);
                        float2 s1 = *reinterpret_cast<const float2*>(S1 + col0);
                        *reinterpret_cast<float2*>(O0 + col0) =
                            make_float2(s0.x + acc[n][0], s0.y + acc[n][1]);
                        *reinterpret_cast<float2*>(O1 + col0) =
                            make_float2(s1.x + acc[n][2], s1.y + acc[n][3]);
                    }
                }
            }
        }
    }
    __syncthreads();

    // ---------------- Phase 2b: column stats from out (L2-hot, coalesced) ------
    {
        int l = t & 255, ch = t >> 8;
        if (l < Ln) {
            const float* p = out + (size_t)b * Cn * Ln + (size_t)(ch * 128) * Ln + l;
            float s1 = 0.f, s2 = 0.f;
            #pragma unroll 8
            for (int c = 0; c < 128; c += 2) {
                float v0 = p[c * Ln], v1 = p[(c + 1) * Ln];
                s1 += v0 + v1;
                s2 += v0 * v0 + v1 * v1;
            }
            atomicAdd(&cs1[l], s1);
            atomicAdd(&cs2[l], s2);
        }
    }
    __syncthreads();

    // ---------------- Phase 3: channel-LN affine P,Q ----------------
    if (t < Ln) {
        float a = 0.5f * s_simw[t];
        float mu_y  = cs1[t] * (1.0f / Cn);
        float var_y = cs2[t] * (1.0f / Cn) - mu_y * mu_y;
        float inv_s = rsqrtf(a * a * var_y + 1e-5f);
        cs1[t] = a * inv_s;
        cs2[t] = -a * mu_y * inv_s;
    }
    if (t >= Ln && t < 200) { cs1[t] = 0.f; cs2[t] = 0.f; }
    __syncthreads();

    // ---------------- Phase 4: spatial standardization (out L2-hot) ----------
    {
        const float4* P4 = reinterpret_cast<const float4*>(cs1);
        const float4* Q4 = reinterpret_cast<const float4*>(cs2);
        bool has2 = (ln + 32) < Ln / 4;
        int g2 = has2 ? (ln + 32) : 0;
        float4 p0 = P4[ln], q0 = Q4[ln];
        float4 p1 = P4[g2], q1 = Q4[g2];

        for (int c = w; c < Cn; c += 16) {
            float4* orow = reinterpret_cast<float4*>(out + ((size_t)b * Cn + c) * Ln);
            float4 y0 = orow[ln];
            float x0[4] = { fmaf(y0.x, p0.x, q0.x), fmaf(y0.y, p0.y, q0.y),
                            fmaf(y0.z, p0.z, q0.z), fmaf(y0.w, p0.w, q0.w) };
            float x1[4] = { 0.f, 0.f, 0.f, 0.f };
            if (has2) {
                float4 y1 = orow[g2];
                x1[0] = fmaf(y1.x, p1.x, q1.x); x1[1] = fmaf(y1.y, p1.y, q1.y);
                x1[2] = fmaf(y1.z, p1.z, q1.z); x1[3] = fmaf(y1.w, p1.w, q1.w);
            }
            float s1 = x0[0] + x0[1] + x0[2] + x0[3];
            float s2 = x0[0]*x0[0] + x0[1]*x0[1] + x0[2]*x0[2] + x0[3]*x0[3];
            if (has2) {
                s1 += x1[0] + x1[1] + x1[2] + x1[3];
                s2 += x1[0]*x1[0] + x1[1]*x1[1] + x1[2]*x1[2] + x1[3]*x1[3];
            }
            #pragma unroll
            for (int o = 16; o > 0; o >>= 1) {
                s1 += __shfl_xor_sync(0xffffffffu, s1, o);
                s2 += __shfl_xor_sync(0xffffffffu, s2, o);
            }
            float mean = s1 * (1.0f / Ln);
            float var  = (s2 - (float)Ln * mean * mean) * (1.0f / (Ln - 1));
            float inv  = 1.0f / (sqrtf(fmaxf(var, 0.f)) + 1e-6f);

            float4 o0 = { (x0[0]-mean)*inv, (x0[1]-mean)*inv, (x0[2]-mean)*inv, (x0[3]-mean)*inv };
            orow[ln] = o0;
            if (has2) {
                float4 o1 = { (x1[0]-mean)*inv, (x1[1]-mean)*inv, (x1[2]-mean)*inv, (x1[3]-mean)*inv };
                orow[g2] = o1;
            }
        }
    }
}

// ============================================================================
extern "C" void kernel_launch(void* const* d_in, const int* in_sizes, int n_in,
                              void* d_out, int out_size)
{
    const float* imf  = (const float*)d_in[0];
    const float* txt  = (const float*)d_in[1];
    const float* sam  = (const float*)d_in[2];
    const float* Wsim = (const float*)d_in[3];
    const float* bsim = (const float*)d_in[4];
    float* out = (float*)d_out;

    // dyn = max(phase1 256*100, phase2 200*100 + 64*100) = 26,400 words
    const int smem = (200 * BWS + 64 * AWS) * (int)sizeof(float);   // 105,600 B
    cudaFuncSetAttribute(k_main, cudaFuncAttributeMaxDynamicSharedMemorySize, smem);
    k_main<<<Bn, NT, smem>>>(imf, txt, sam, Wsim, bsim, out);
}

// round 17
// speedup vs baseline: 1.1960x; 1.0182x over previous
#include <cuda_runtime.h>
#include <cuda_bf16.h>
#include <math.h>
#include <stdint.h>

#define Bn 512
#define Cn 256
#define Ln 196
#define Dn 512
#define XWS 100     // phase-1 X word stride ([c][l] natural): 400B % 128 = 16
#define BWS 100     // phase-2 B word stride
#define AWS 100     // phase-2 A word stride
#define NT 512      // threads per CTA (16 warps) -> 2 CTAs/SM

// raw exp matrix, bf16x2 words: [b][l][98 words]
static __device__ uint32_t g_attnw[(size_t)Bn * Ln * 98];

__device__ __forceinline__ uint32_t smem_u32(const void* p) {
    uint32_t a;
    asm("{ .reg .u64 t; cvta.to.shared.u64 t, %1; cvt.u32.u64 %0, t; }" : "=r"(a) : "l"(p));
    return a;
}
#define LDSM_X4(r0, r1, r2, r3, a) \
    asm volatile("ldmatrix.sync.aligned.m8n8.x4.shared.b16 {%0,%1,%2,%3}, [%4];" \
        : "=r"(r0), "=r"(r1), "=r"(r2), "=r"(r3) : "r"(a))
#define LDSM_X2(r0, r1, a) \
    asm volatile("ldmatrix.sync.aligned.m8n8.x2.shared.b16 {%0,%1}, [%2];" \
        : "=r"(r0), "=r"(r1) : "r"(a))
#define LDSM_X4T(r0, r1, r2, r3, a) \
    asm volatile("ldmatrix.sync.aligned.m8n8.x4.trans.shared.b16 {%0,%1,%2,%3}, [%4];" \
        : "=r"(r0), "=r"(r1), "=r"(r2), "=r"(r3) : "r"(a))
#define LDSM_X2T(r0, r1, a) \
    asm volatile("ldmatrix.sync.aligned.m8n8.x2.trans.shared.b16 {%0,%1}, [%2];" \
        : "=r"(r0), "=r"(r1) : "r"(a))
#define BAR_GRP(id) \
    asm volatile("bar.sync %0, 128;" :: "r"(id) : "memory")

__device__ __forceinline__ void mma16(float* d, uint32_t a0, uint32_t a1, uint32_t a2,
                                      uint32_t a3, uint32_t b0, uint32_t b1) {
    asm volatile("mma.sync.aligned.m16n8k16.row.col.f32.bf16.bf16.f32 "
        "{%0,%1,%2,%3}, {%4,%5,%6,%7}, {%8,%9}, {%0,%1,%2,%3};"
        : "+f"(d[0]), "+f"(d[1]), "+f"(d[2]), "+f"(d[3])
        : "r"(a0), "r"(a1), "r"(a2), "r"(a3), "r"(b0), "r"(b1));
}
__device__ __forceinline__ void mma8b(float* d, uint32_t a0, uint32_t a1, uint32_t b0) {
    asm volatile("mma.sync.aligned.m16n8k8.row.col.f32.bf16.bf16.f32 "
        "{%0,%1,%2,%3}, {%4,%5}, {%6}, {%0,%1,%2,%3};"
        : "+f"(d[0]), "+f"(d[1]), "+f"(d[2]), "+f"(d[3])
        : "r"(a0), "r"(a1), "r"(b0));
}

// ============================================================================
// Mega-kernel: one CTA per batch, 512 threads (16 warps), 2 CTAs/SM.
// dyn smem: phase1 Xn 256x100 words ([c][l], ldmatrix.trans);
//           phase2 [Bw 200x100][A-slice 64x100] with per-group named barriers.
// ============================================================================
__global__ __launch_bounds__(NT, 2) void k_main(
    const float* __restrict__ imf, const float* __restrict__ txt,
    const float* __restrict__ sam, const float* __restrict__ Wsim,
    const float* __restrict__ bsim, float* __restrict__ out)
{
    extern __shared__ float dyn[];          // 105,600 B
    __shared__ float red[3][16];
    __shared__ float s_simw[200];
    __shared__ __align__(16) float cs1[200];
    __shared__ __align__(16) float cs2[200];
    __shared__ __align__(16) float s_rsum[208];
    __shared__ float s_inv[208];

    int b = blockIdx.x, t = threadIdx.x, w = t >> 5, ln = t & 31;
    int g = ln >> 2, tig = ln & 3;
    const float* Sb = sam + (size_t)b * Cn * Ln;
    uint32_t* Ag = g_attnw + (size_t)b * Ln * 98;

    // ---------------- Phase 0: simw; zero accumulators ----------------
    {
        float* s_imd = dyn;
        float a0 = imf[(size_t)b * Dn + t];
        float c0 = txt[(size_t)b * Dn + t];
        float ni = a0*a0, nt = c0*c0, ct = a0*c0;
        #pragma unroll
        for (int o = 16; o > 0; o >>= 1) {
            ni += __shfl_xor_sync(0xffffffffu, ni, o);
            nt += __shfl_xor_sync(0xffffffffu, nt, o);
            ct += __shfl_xor_sync(0xffffffffu, ct, o);
        }
        if (ln == 0) { red[0][w] = ni; red[1][w] = nt; red[2][w] = ct; }
        if (t < 200) { cs1[t] = 0.f; cs2[t] = 0.f; }
        if (t < 208) { s_inv[t] = 0.f; s_rsum[t] = 0.f; }
        __syncthreads();
        float nI = 0.f, nT = 0.f, cT = 0.f;
        #pragma unroll
        for (int j = 0; j < 16; j++) { nI += red[0][j]; nT += red[1][j]; cT += red[2][j]; }
        float invI = 1.0f / fmaxf(sqrtf(nI), 1e-12f);
        float invT = 1.0f / fmaxf(sqrtf(nT), 1e-12f);
        float cross = cT * invI * invT;
        s_imd[t] = a0 * invI;
        __syncthreads();

        const float4* s4 = reinterpret_cast<const float4*>(s_imd);
        for (int r = w; r < Ln; r += 16) {
            const float4* wr = reinterpret_cast<const float4*>(Wsim + (size_t)r * Dn);
            float acc = 0.f;
            #pragma unroll
            for (int i = 0; i < 4; i++) {
                float4 a = wr[ln + i * 32];
                float4 s = s4[ln + i * 32];
                acc += a.x*s.x + a.y*s.y + a.z*s.z + a.w*s.w;
            }
            #pragma unroll
            for (int o = 16; o > 0; o >>= 1) acc += __shfl_xor_sync(0xffffffffu, acc, o);
            if (ln == 0) {
                acc += bsim[r];
                s_simw[r] = cross * (1.0f / (1.0f + __expf(-acc))) * 0.1f;
            }
        }
    }
    __syncthreads();

    // ---------------- Phase 1: GEMM1 (bf16, ldmatrix.trans) -> exp -> g_attnw --
    {
        uint32_t* Xn = reinterpret_cast<uint32_t*>(dyn);   // 256 x XWS  ([c][l])
        uint32_t Xs = smem_u32(Xn);

        // column norms (coalesced along l)
        {
            int l = t & 255, ch = t >> 8;
            if (l < Ln) {
                const float* p = Sb + (size_t)(ch * 128) * Ln + l;
                float s0 = 0.f, s1 = 0.f;
                #pragma unroll 8
                for (int c = 0; c < 128; c += 2) {
                    float v0 = p[c * Ln], v1 = p[(c + 1) * Ln];
                    s0 += v0 * v0; s1 += v1 * v1;
                }
                atomicAdd(&s_inv[l], s0 + s1);
            }
        }
        // zero pad words 98,99 of every row
        {
            int c = t >> 1;
            Xn[c * XWS + 98 + (t & 1)] = 0u;
        }
        __syncthreads();
        if (t < Ln) s_inv[t] = 0.25f / fmaxf(sqrtf(s_inv[t]), 1e-12f);
        __syncthreads();

        // stage Xn[c][l] = bf16(sam[c][l] * inv[l]) -- fully coalesced
        {
            int c = t / 25, g4 = t - c * 25;   // 512 = 20*25 + 12
            for (int idx = t; idx < 256 * 25; idx += NT) {
                int l0 = g4 * 8;
                float4 va, vb = make_float4(0.f, 0.f, 0.f, 0.f);
                const float* src = Sb + (size_t)c * Ln + l0;
                va = *reinterpret_cast<const float4*>(src);        // l0 <= 192 < 196
                if (l0 + 4 < Ln) vb = *reinterpret_cast<const float4*>(src + 4);
                float4 r0 = *reinterpret_cast<const float4*>(s_inv + l0);
                float4 r1 = *reinterpret_cast<const float4*>(s_inv + l0 + 4);
                __nv_bfloat162 h0 = __floats2bfloat162_rn(va.x * r0.x, va.y * r0.y);
                __nv_bfloat162 h1 = __floats2bfloat162_rn(va.z * r0.z, va.w * r0.w);
                __nv_bfloat162 h2 = __floats2bfloat162_rn(vb.x * r1.x, vb.y * r1.y);
                __nv_bfloat162 h3 = __floats2bfloat162_rn(vb.z * r1.z, vb.w * r1.w);
                uint32_t* dst = Xn + c * XWS;
                int w2 = g4 * 4;
                dst[w2]     = *reinterpret_cast<uint32_t*>(&h0);
                dst[w2 + 1] = *reinterpret_cast<uint32_t*>(&h1);
                dst[w2 + 2] = *reinterpret_cast<uint32_t*>(&h2);
                dst[w2 + 3] = *reinterpret_cast<uint32_t*>(&h3);
                g4 += 12; c += 20;
                if (g4 >= 25) { g4 -= 25; c += 1; }
            }
        }
        __syncthreads();

        // trans lane roles
        int rAT  = (ln & 7) + (ln >> 4) * 8;          // A: k-row pattern
        int aCol = ((ln >> 3) & 1) * 4;               // A: +8 m -> +4 words
        int rBT  = (ln & 7) + ((ln >> 3) & 1) * 8;    // B x4: k-row pattern
        int bCol = (ln >> 4) * 4;                     // B x4: +8 n -> +4 words
        int rB2T = ln & 15;                           // B x2: k rows 0..15

        // 64 jobs: job<4 -> mt0 slices (7,6,6,6); else mt 1..12 x 5 slices of 5
        for (int r = 0; r < 4; r++) {
            int job = r * 16 + w;
            int mt, cb, nfr;
            if (job < 4) {
                mt = 0;
                nfr = (job == 0) ? 7 : 6;
                cb  = (job == 0) ? 0 : (56 + (job - 1) * 48);
            } else {
                int j = job - 4;
                mt = 1 + j / 5;
                cb = (j % 5) * 40;
                nfr = 5;
            }

            float acc[7][4];
            #pragma unroll
            for (int n = 0; n < 7; n++)
                #pragma unroll
                for (int j2 = 0; j2 < 4; j2++) acc[n][j2] = 0.f;

            uint32_t aad = Xs + ((rAT * XWS) + mt * 8 + aCol) * 4;
            uint32_t bad[4];
            #pragma unroll
            for (int fp = 0; fp < 4; fp++) {
                bool full = (fp * 2 + 1 < nfr);
                int rk = full ? rBT : rB2T;
                int cw = (cb >> 1) + fp * 8 + (full ? bCol : 0);
                bad[fp] = Xs + ((rk * XWS) + cw) * 4;
            }

            #pragma unroll 4
            for (int ks = 0; ks < 16; ks++) {
                uint32_t a0, a1, a2, a3;
                LDSM_X4T(a0, a1, a2, a3, aad); aad += 16 * XWS * 4;
                #pragma unroll
                for (int fp = 0; fp < 4; fp++) {
                    if (fp * 2 < nfr) {
                        if (fp * 2 + 1 < nfr) {
                            uint32_t b0, b1, b2, b3;
                            LDSM_X4T(b0, b1, b2, b3, bad[fp]);
                            mma16(acc[2*fp],   a0, a1, a2, a3, b0, b1);
                            mma16(acc[2*fp+1], a0, a1, a2, a3, b2, b3);
                        } else {
                            uint32_t b0, b1;
                            LDSM_X2T(b0, b1, bad[fp]);
                            mma16(acc[2*fp], a0, a1, a2, a3, b0, b1);
                        }
                        bad[fp] += 16 * XWS * 4;
                    }
                }
            }

            // epilogue: exp -> row sums + bf16x2 store to g_attnw row l
            #pragma unroll
            for (int rh = 0; rh < 2; rh++) {
                int l = mt * 16 + g + 8 * rh;
                float e[7][2];
                float sum = 0.f;
                #pragma unroll
                for (int n = 0; n < 7; n++) {
                    if (n < nfr) {
                        int col0 = cb + n * 8 + 2 * tig;
                        float e0 = __expf(acc[n][rh*2]);
                        float e1 = __expf(acc[n][rh*2+1]);
                        e[n][0] = e0; e[n][1] = e1;
                        if (col0 < Ln) sum += e0 + e1;
                    }
                }
                sum += __shfl_xor_sync(0xffffffffu, sum, 1);
                sum += __shfl_xor_sync(0xffffffffu, sum, 2);
                if (l < Ln) {
                    if (tig == 0) atomicAdd(&s_rsum[l], sum);
                    uint32_t* arow = Ag + (size_t)l * 98;
                    #pragma unroll
                    for (int n = 0; n < 7; n++) {
                        if (n < nfr) {
                            int col0 = cb + n * 8 + 2 * tig;
                            if (col0 < Ln) {
                                __nv_bfloat162 h = __floats2bfloat162_rn(e[n][0], e[n][1]);
                                arow[col0 >> 1] = *reinterpret_cast<uint32_t*>(&h);
                            }
                        }
                    }
                }
            }
        }
    }
    __syncthreads();
    if (t < Ln) s_rsum[t] = 1.0f / s_rsum[t];
    __syncthreads();

    // ---------------- Phase 2: GEMM2 (bf16, ldmatrix); B resident;
    //                  A staged per 4-warp group with NAMED barriers ----------
    {
        uint32_t* Bw = reinterpret_cast<uint32_t*>(dyn);             // 200 x 100
        uint32_t* Aw = reinterpret_cast<uint32_t*>(dyn) + 200 * BWS; // 64 x 100
        uint32_t Bs = smem_u32(Bw);
        uint32_t As = smem_u32(Aw);

        // stage B[m][w2] from g_attnw (rows>=196 and words 98,99 zero)
        {
            int m = t / 50, p2 = t - m * 50;      // 512 = 10*50 + 12
            for (int idx = t; idx < 200 * 50; idx += NT) {
                int w2 = 2 * p2;
                uint2 v = make_uint2(0u, 0u);
                if (m < Ln && w2 < 98)
                    v = *reinterpret_cast<const uint2*>(g_attnw + ((size_t)b * Ln + m) * 98 + w2);
                Bw[m * BWS + w2]     = v.x;
                Bw[m * BWS + w2 + 1] = v.y;
                p2 += 12; m += 10;
                if (p2 >= 50) { p2 -= 50; m += 1; }
            }
        }
        __syncthreads();   // B visible to all groups

        int rApat = (ln & 7) + ((ln >> 3) & 1) * 8;
        int khA   = ln >> 4;
        int rBpat = (ln & 7) + (ln >> 4) * 8;
        int khBp  = (ln >> 3) & 1;
        int l15   = ln & 15;
        int rB2   = l15 & 7;
        int khB2  = l15 >> 3;

        int gid  = w >> 2;          // 4-warp group 0..3 (shares A rows 16*gid..+16)
        int t128 = t & 127;         // thread within group
        int barid = 1 + gid;
        uint32_t* Agrp = Aw + gid * 16 * AWS;

        for (int r = 0; r < 4; r++) {
            // group-local stage of 16 A rows: global rows (4r+gid)*16 .. +16
            {
                int base = 64 * r + 16 * gid;
                for (int idx = t128; idx < 16 * 25; idx += 128) {
                    int cl = idx / 25, g4 = idx - cl * 25;
                    int l0 = g4 * 8;
                    float4 va, vb = make_float4(0.f, 0.f, 0.f, 0.f);
                    const float* src = Sb + (size_t)(base + cl) * Ln + l0;
                    va = *reinterpret_cast<const float4*>(src);
                    if (l0 + 4 < Ln) vb = *reinterpret_cast<const float4*>(src + 4);
                    float4 r0 = *reinterpret_cast<const float4*>(s_rsum + l0);
                    float4 r1 = *reinterpret_cast<const float4*>(s_rsum + l0 + 4);
                    __nv_bfloat162 h0 = __floats2bfloat162_rn(va.x * r0.x, va.y * r0.y);
                    __nv_bfloat162 h1 = __floats2bfloat162_rn(va.z * r0.z, va.w * r0.w);
                    __nv_bfloat162 h2 = __floats2bfloat162_rn(vb.x * r1.x, vb.y * r1.y);
                    __nv_bfloat162 h3 = __floats2bfloat162_rn(vb.z * r1.z, vb.w * r1.w);
                    uint32_t* dst = Agrp + cl * AWS;
                    int w2 = g4 * 4;
                    dst[w2]     = *reinterpret_cast<uint32_t*>(&h0);
                    dst[w2 + 1] = *reinterpret_cast<uint32_t*>(&h1);
                    dst[w2 + 2] = *reinterpret_cast<uint32_t*>(&h2);
                    dst[w2 + 3] = *reinterpret_cast<uint32_t*>(&h3);
                }
            }
            BAR_GRP(barid);   // staging visible within group

            int q = (r + w) & 3;
            int mtg = 4 * r + gid;
            int cbm = (q == 0) ? 0 : (q == 1) ? 56 : (q == 2) ? 104 : 160;
            int nfr = (q == 0 || q == 2) ? 7 : (q == 1) ? 6 : 5;

            float acc[7][4];
            #pragma unroll
            for (int n = 0; n < 7; n++)
                #pragma unroll
                for (int j = 0; j < 4; j++) acc[n][j] = 0.f;

            uint32_t aad = As + (((gid * 16 + rApat) * AWS) + khA * 4) * 4;
            uint32_t bad[4];
            #pragma unroll
            for (int fp = 0; fp < 4; fp++) {
                bool full = (fp * 2 + 1 < nfr);
                int rb = cbm + fp * 16 + (full ? rBpat : rB2);
                int kh = full ? khBp : khB2;
                bad[fp] = Bs + ((rb * BWS) + kh * 4) * 4;
            }

            #pragma unroll 4
            for (int ks = 0; ks < 12; ks++) {
                uint32_t a0, a1, a2, a3;
                LDSM_X4(a0, a1, a2, a3, aad); aad += 32;
                #pragma unroll
                for (int fp = 0; fp < 4; fp++) {
                    if (fp * 2 < nfr) {
                        if (fp * 2 + 1 < nfr) {
                            uint32_t b0, b1, b2, b3;
                            LDSM_X4(b0, b1, b2, b3, bad[fp]);
                            mma16(acc[2*fp],   a0, a1, a2, a3, b0, b1);
                            mma16(acc[2*fp+1], a0, a1, a2, a3, b2, b3);
                        } else {
                            uint32_t b0, b1;
                            LDSM_X2(b0, b1, bad[fp]);
                            mma16(acc[2*fp], a0, a1, a2, a3, b0, b1);
                        }
                        bad[fp] += 32;
                    }
                }
            }
            // k8 tail (k = 192..199; elements 196..199 are zero pads)
            {
                uint32_t a0, a1;
                LDSM_X2(a0, a1, As + (((gid * 16 + l15) * AWS) + 96) * 4);
                uint32_t c0, c1, c2, c3, d0, d1, d2, d3;
                LDSM_X4(c0, c1, c2, c3, Bs + (((cbm + ln) * BWS) + 96) * 4);
                LDSM_X4(d0, d1, d2, d3, Bs + (((cbm + 32 + ln) * BWS) + 96) * 4);
                mma8b(acc[0], a0, a1, c0);
                mma8b(acc[1], a0, a1, c1);
                mma8b(acc[2], a0, a1, c2);
                mma8b(acc[3], a0, a1, c3);
                mma8b(acc[4], a0, a1, d0);
                if (nfr > 5) mma8b(acc[5], a0, a1, d1);
                if (nfr > 6) mma8b(acc[6], a0, a1, d2);
            }
            BAR_GRP(barid);   // all group reads of A done -> safe to restage

            // epilogue: y = sam + D -> out (after bar so next stage can start)
            int c0r = mtg * 16 + g;
            int c1r = c0r + 8;
            const float* S0 = Sb + (size_t)c0r * Ln;
            const float* S1 = Sb + (size_t)c1r * Ln;
            float* O0 = out + ((size_t)b * Cn + c0r) * Ln;
            float* O1 = out + ((size_t)b * Cn + c1r) * Ln;
            #pragma unroll
            for (int n = 0; n < 7; n++) {
                if (n < nfr) {
                    int col0 = cbm + n * 8 + 2 * tig;
                    if (col0 < Ln) {
                        float2 s0 = *reinterpret_cast<const float2*>(S0 + col0);
                        float2 s1 = *reinterpret_cast<const float2*>(S1 + col0);
                        *reinterpret_cast<float2*>(O0 + col0) =
                            make_float2(s0.x + acc[n][0], s0.y + acc[n][1]);
                        *reinterpret_cast<float2*>(O1 + col0) =
                            make_float2(s1.x + acc[n][2], s1.y + acc[n][3]);
                    }
                }
            }
        }
    }
    __syncthreads();

    // ---------------- Phase 2b: column stats from out (L2-hot, coalesced) ------
    {
        int l = t & 255, ch = t >> 8;
        if (l < Ln) {
            const float* p = out + (size_t)b * Cn * Ln + (size_t)(ch * 128) * Ln + l;
            float s1 = 0.f, s2 = 0.f;
            #pragma unroll 8
            for (int c = 0; c < 128; c += 2) {
                float v0 = p[c * Ln], v1 = p[(c + 1) * Ln];
                s1 += v0 + v1;
                s2 += v0 * v0 + v1 * v1;
            }
            atomicAdd(&cs1[l], s1);
            atomicAdd(&cs2[l], s2);
        }
    }
    __syncthreads();

    // ---------------- Phase 3: channel-LN affine P,Q ----------------
    if (t < Ln) {
        float a = 0.5f * s_simw[t];
        float mu_y  = cs1[t] * (1.0f / Cn);
        float var_y = cs2[t] * (1.0f / Cn) - mu_y * mu_y;
        float inv_s = rsqrtf(a * a * var_y + 1e-5f);
        cs1[t] = a * inv_s;
        cs2[t] = -a * mu_y * inv_s;
    }
    if (t >= Ln && t < 200) { cs1[t] = 0.f; cs2[t] = 0.f; }
    __syncthreads();

    // ---------------- Phase 4: spatial standardization (out L2-hot) ----------
    {
        const float4* P4 = reinterpret_cast<const float4*>(cs1);
        const float4* Q4 = reinterpret_cast<const float4*>(cs2);
        bool has2 = (ln + 32) < Ln / 4;
        int g2 = has2 ? (ln + 32) : 0;
        float4 p0 = P4[ln], q0 = Q4[ln];
        float4 p1 = P4[g2], q1 = Q4[g2];

        for (int c = w; c < Cn; c += 16) {
            float4* orow = reinterpret_cast<float4*>(out + ((size_t)b * Cn + c) * Ln);
            float4 y0 = orow[ln];
            float x0[4] = { fmaf(y0.x, p0.x, q0.x), fmaf(y0.y, p0.y, q0.y),
                            fmaf(y0.z, p0.z, q0.z), fmaf(y0.w, p0.w, q0.w) };
            float x1[4] = { 0.f, 0.f, 0.f, 0.f };
            if (has2) {
                float4 y1 = orow[g2];
                x1[0] = fmaf(y1.x, p1.x, q1.x); x1[1] = fmaf(y1.y, p1.y, q1.y);
                x1[2] = fmaf(y1.z, p1.z, q1.z); x1[3] = fmaf(y1.w, p1.w, q1.w);
            }
            float s1 = x0[0] + x0[1] + x0[2] + x0[3];
            float s2 = x0[0]*x0[0] + x0[1]*x0[1] + x0[2]*x0[2] + x0[3]*x0[3];
            if (has2) {
                s1 += x1[0] + x1[1] + x1[2] + x1[3];
                s2 += x1[0]*x1[0] + x1[1]*x1[1] + x1[2]*x1[2] + x1[3]*x1[3];
            }
            #pragma unroll
            for (int o = 16; o > 0; o >>= 1) {
                s1 += __shfl_xor_sync(0xffffffffu, s1, o);
                s2 += __shfl_xor_sync(0xffffffffu, s2, o);
            }
            float mean = s1 * (1.0f / Ln);
            float var  = (s2 - (float)Ln * mean * mean) * (1.0f / (Ln - 1));
            float inv  = 1.0f / (sqrtf(fmaxf(var, 0.f)) + 1e-6f);

            float4 o0 = { (x0[0]-mean)*inv, (x0[1]-mean)*inv, (x0[2]-mean)*inv, (x0[3]-mean)*inv };
            orow[ln] = o0;
            if (has2) {
                float4 o1 = { (x1[0]-mean)*inv, (x1[1]-mean)*inv, (x1[2]-mean)*inv, (x1[3]-mean)*inv };
                orow[g2] = o1;
            }
        }
    }
}

// ============================================================================
extern "C" void kernel_launch(void* const* d_in, const int* in_sizes, int n_in,
                              void* d_out, int out_size)
{
    const float* imf  = (const float*)d_in[0];
    const float* txt  = (const float*)d_in[1];
    const float* sam  = (const float*)d_in[2];
    const float* Wsim = (const float*)d_in[3];
    const float* bsim = (const float*)d_in[4];
    float* out = (float*)d_out;

    // dyn = max(phase1 256*100, phase2 200*100 + 64*100) = 26,400 words
    const int smem = (200 * BWS + 64 * AWS) * (int)sizeof(float);   // 105,600 B
    cudaFuncSetAttribute(k_main, cudaFuncAttributeMaxDynamicSharedMemorySize, smem);
    k_main<<<Bn, NT, smem>>>(imf, txt, sam, Wsim, bsim, out);
}